// round 15
// baseline (speedup 1.0000x reference)
#include <cuda_runtime.h>
#include <cuda_bf16.h>
#include <math.h>
#include <cstdint>

#define BB 2
#define LSEQ 1024
#define DM 256
#define DI 512
#define DS 64
#define NH 8
#define HD 64
#define CD 640
#define DIP 1160
#define M2 (BB*LSEQ)
#define NLAYERS 2
#define NCHUNK 16
#define QCH 64

// ------------------------- fp32 scratch -------------------------------------
static constexpr size_t OFF_H    = 0;
static constexpr size_t OFF_ZX   = OFF_H    + (size_t)2*M2*DM;
static constexpr size_t OFF_CC   = OFF_ZX   + (size_t)2*M2*DIP;
static constexpr size_t OFF_Y    = OFF_CC   + (size_t)2*M2*DS;
static constexpr size_t OFF_GATE = OFF_Y    + (size_t)2*M2*DI;
static constexpr size_t OFF_HLOC = OFF_GATE + (size_t)M2*2*DM;
static constexpr size_t OFF_SDT  = OFF_HLOC + (size_t)32*NCHUNK*HD*DS;
static constexpr size_t OFF_CSUM = OFF_SDT  + (size_t)32*LSEQ;
static constexpr size_t SCRATCH_TOTAL = OFF_CSUM + (size_t)32*NCHUNK;

__device__ float g_scratch[SCRATCH_TOTAL];

// ------------------------- bf16 hi/lo scratch -------------------------------
static constexpr size_t B_ACTH  = 0;
static constexpr size_t B_ACTL  = B_ACTH  + (size_t)2*M2*DM;
static constexpr size_t B_NRMH  = B_ACTL  + (size_t)2*M2*DM;
static constexpr size_t B_NRML  = B_NRMH  + (size_t)2*M2*DI;
static constexpr size_t B_COMBH = B_NRML  + (size_t)2*M2*DI;
static constexpr size_t B_COMBL = B_COMBH + (size_t)M2*2*DM;
static constexpr size_t B_WINH  = B_COMBL + (size_t)M2*2*DM;
static constexpr size_t B_WINL  = B_WINH  + (size_t)2*NLAYERS*DIP*DM;
static constexpr size_t B_WOUTH = B_WINL  + (size_t)2*NLAYERS*DIP*DM;
static constexpr size_t B_WOUTL = B_WOUTH + (size_t)2*NLAYERS*DM*DI;
static constexpr size_t B_WFUSH = B_WOUTL + (size_t)2*NLAYERS*DM*DI;
static constexpr size_t B_WFUSL = B_WFUSH + (size_t)(2*DM)*(2*DM);
static constexpr size_t BF_TOTAL = B_WFUSL + (size_t)(2*DM)*(2*DM);

__device__ __align__(16) __nv_bfloat16 g_bf[BF_TOTAL];

typedef unsigned long long ull;

// ---- HMMA helpers -----------------------------------------------------------
__device__ __forceinline__ uint32_t smem_u32(const void* p) {
    uint32_t a;
    asm("{ .reg .u64 t; cvta.to.shared.u64 t, %1; cvt.u32.u64 %0, t; }" : "=r"(a) : "l"(p));
    return a;
}
__device__ __forceinline__ void ldsm_x4(uint32_t* r, uint32_t addr) {
    asm volatile("ldmatrix.sync.aligned.m8n8.x4.shared.b16 {%0,%1,%2,%3}, [%4];"
        : "=r"(r[0]), "=r"(r[1]), "=r"(r[2]), "=r"(r[3]) : "r"(addr));
}
__device__ __forceinline__ void mma16816(float* d, const uint32_t* a, const uint32_t* b) {
    asm volatile("mma.sync.aligned.m16n8k16.row.col.f32.bf16.bf16.f32 "
        "{%0,%1,%2,%3}, {%4,%5,%6,%7}, {%8,%9}, {%0,%1,%2,%3};"
        : "+f"(d[0]), "+f"(d[1]), "+f"(d[2]), "+f"(d[3])
        : "r"(a[0]), "r"(a[1]), "r"(a[2]), "r"(a[3]), "r"(b[0]), "r"(b[1]));
}
__device__ __forceinline__ void split2(float v, __nv_bfloat16& h, __nv_bfloat16& l) {
    h = __float2bfloat16(v);
    l = __float2bfloat16(v - __bfloat162float(h));
}
__device__ __forceinline__ void cp16(uint32_t d, const void* s) {
    asm volatile("cp.async.ca.shared.global [%0], [%1], 16;" :: "r"(d), "l"(s));
}
__device__ __forceinline__ void cp16z(uint32_t d, const void* s, int sz) {
    asm volatile("cp.async.ca.shared.global [%0], [%1], 16, %2;" :: "r"(d), "l"(s), "r"(sz));
}
#define CP_COMMIT() asm volatile("cp.async.commit_group;" ::: "memory")
#define CP_WAIT0()  asm volatile("cp.async.wait_group 0;" ::: "memory")

// ---------------- fused fp32 -> bf16 hi/lo conversion (3 weight arrays) ------
__global__ void k_cvt3(const float* __restrict__ w1, int n1,
                       const float* __restrict__ w2, int n2,
                       const float* __restrict__ w3, int n3) {
    int i = (blockIdx.x*blockDim.x + threadIdx.x)*4;
    const float* x; size_t oh, ol; int base;
    if (i < n1)            { x = w1; oh = B_WINH;  ol = B_WINL;  base = 0; }
    else if (i < n1 + n2)  { x = w2; oh = B_WOUTH; ol = B_WOUTL; base = n1; }
    else if (i < n1+n2+n3) { x = w3; oh = B_WFUSH; ol = B_WFUSL; base = n1 + n2; }
    else return;
    int ii = i - base;
    float4 v = *(const float4*)(x + ii);
    float vv[4] = {v.x, v.y, v.z, v.w};
#pragma unroll
    for (int k = 0; k < 4; k++) {
        __nv_bfloat16 h, l;
        split2(vv[k], h, l);
        g_bf[oh + ii + k] = h;
        g_bf[ol + ii + k] = l;
    }
}

// ---------------- HMMA split-bf16 GEMM 128x64, cp.async double-buffered ------
#define KC 32
#define SA 40
#define GA_BUF 10240
#define GW_BUF 5120
#define GEMM_SMEM (2*GA_BUF*2 + 2*GW_BUF*2)

__global__ __launch_bounds__(256) void k_mma_gemm(
        size_t oAh, size_t oAl, size_t oWh, size_t oWl,
        float* __restrict__ C, int M, int N, int K,
        long sAz, long sWz, long sCz,
        size_t oCh, size_t oCl, int wrBf) {
    const __nv_bfloat16* Ah = g_bf + oAh + (long)blockIdx.z * sAz;
    const __nv_bfloat16* Al = g_bf + oAl + (long)blockIdx.z * sAz;
    const __nv_bfloat16* Wh = g_bf + oWh + (long)blockIdx.z * sWz;
    const __nv_bfloat16* Wl = g_bf + oWl + (long)blockIdx.z * sWz;
    C += (long)blockIdx.z * sCz;
    size_t oChz = oCh + (long)blockIdx.z * sCz;
    size_t oClz = oCl + (long)blockIdx.z * sCz;

    extern __shared__ char gsm[];
    uint32_t aAh = smem_u32(gsm);
    uint32_t aAl = aAh + 2*GA_BUF;
    uint32_t aWh = aAl + 2*GA_BUF;
    uint32_t aWl = aWh + 2*GW_BUF;

    int tid = threadIdx.x;
    int warp = tid >> 5, lane = tid & 31;
    int wm = warp & 3, wn = warp >> 2;
    int m0 = blockIdx.y * 128, n0 = blockIdx.x * 64;

    float acc[2][4][4];
#pragma unroll
    for (int i = 0; i < 2; i++)
#pragma unroll
        for (int j = 0; j < 4; j++)
#pragma unroll
            for (int k = 0; k < 4; k++) acc[i][j][k] = 0.f;

    int a_r  = (lane & 15);
    int a_k  = (lane >> 4) << 3;

    int srA = tid >> 2, scA = (tid & 3) * 8;
    int srW = tid >> 2, scW = (tid & 3) * 8;
    int wrow = n0 + srW;
    int wsz = (wrow < N) ? 16 : 0;
    int wclamp = (wrow < N) ? wrow : (N - 1);

    int KT = K / KC;

    {
        int k0 = 0;
#pragma unroll
        for (int i = 0; i < 2; i++) {
            int r = srA + i*64;
            uint32_t d = (uint32_t)((r*SA + scA) * 2);
            cp16(aAh + d, Ah + (size_t)(m0 + r)*K + k0 + scA);
            cp16(aAl + d, Al + (size_t)(m0 + r)*K + k0 + scA);
        }
        uint32_t d = (uint32_t)((srW*SA + scW) * 2);
        cp16z(aWh + d, Wh + (size_t)wclamp*K + k0 + scW, wsz);
        cp16z(aWl + d, Wl + (size_t)wclamp*K + k0 + scW, wsz);
        CP_COMMIT();
    }

    int buf = 0;
    for (int c = 0; c < KT; c++) {
        CP_WAIT0();
        __syncthreads();
        if (c + 1 < KT) {
            int k0 = (c + 1) * KC;
            uint32_t oA = (uint32_t)((buf ^ 1) * GA_BUF);
            uint32_t oW = (uint32_t)((buf ^ 1) * GW_BUF);
#pragma unroll
            for (int i = 0; i < 2; i++) {
                int r = srA + i*64;
                uint32_t d = oA + (uint32_t)((r*SA + scA) * 2);
                cp16(aAh + d, Ah + (size_t)(m0 + r)*K + k0 + scA);
                cp16(aAl + d, Al + (size_t)(m0 + r)*K + k0 + scA);
            }
            uint32_t d = oW + (uint32_t)((srW*SA + scW) * 2);
            cp16z(aWh + d, Wh + (size_t)wclamp*K + k0 + scW, wsz);
            cp16z(aWl + d, Wl + (size_t)wclamp*K + k0 + scW, wsz);
            CP_COMMIT();
        }

        uint32_t bAh = aAh + buf*GA_BUF, bAl = aAl + buf*GA_BUF;
        uint32_t bWh = aWh + buf*GW_BUF, bWl = aWl + buf*GW_BUF;
#pragma unroll
        for (int km = 0; km < 2; km++) {
            uint32_t ah[2][4], al[2][4], bh[4][2], bl[4][2];
#pragma unroll
            for (int mi = 0; mi < 2; mi++) {
                int off = ((wm*32 + mi*16 + a_r)*SA + km*16 + a_k) * 2;
                ldsm_x4(ah[mi], bAh + off);
                ldsm_x4(al[mi], bAl + off);
            }
#pragma unroll
            for (int np = 0; np < 2; np++) {
                int row = wn*32 + (np*2 + ((lane >> 4) & 1))*8 + (lane & 7);
                int off = (row*SA + km*16 + ((lane >> 3) & 1) * 8) * 2;
                uint32_t t4[4];
                ldsm_x4(t4, bWh + off);
                bh[np*2][0] = t4[0]; bh[np*2][1] = t4[1];
                bh[np*2+1][0] = t4[2]; bh[np*2+1][1] = t4[3];
                ldsm_x4(t4, bWl + off);
                bl[np*2][0] = t4[0]; bl[np*2][1] = t4[1];
                bl[np*2+1][0] = t4[2]; bl[np*2+1][1] = t4[3];
            }
#pragma unroll
            for (int mi = 0; mi < 2; mi++)
#pragma unroll
                for (int ni = 0; ni < 4; ni++) {
                    mma16816(acc[mi][ni], ah[mi], bh[ni]);
                    mma16816(acc[mi][ni], ah[mi], bl[ni]);
                    mma16816(acc[mi][ni], al[mi], bh[ni]);
                }
        }
        __syncthreads();
        buf ^= 1;
    }

#pragma unroll
    for (int mi = 0; mi < 2; mi++) {
#pragma unroll
        for (int ni = 0; ni < 4; ni++) {
            int m = m0 + wm*32 + mi*16 + (lane >> 2);
            int n = n0 + wn*32 + ni*8 + (lane & 3)*2;
            if (n < N) {
#pragma unroll
                for (int hrow = 0; hrow < 2; hrow++) {
                    int mm = m + hrow*8;
                    float v0 = acc[mi][ni][hrow*2 + 0];
                    float v1 = acc[mi][ni][hrow*2 + 1];
                    *(float2*)(C + (size_t)mm*N + n) = make_float2(v0, v1);
                    if (wrBf) {
                        __nv_bfloat16 h0, l0, h1, l1;
                        split2(v0, h0, l0); split2(v1, h1, l1);
                        __nv_bfloat162 hh; hh.x = h0; hh.y = h1;
                        __nv_bfloat162 ll; ll.x = l0; ll.y = l1;
                        *(__nv_bfloat162*)(g_bf + oChz + (size_t)mm*N + n) = hh;
                        *(__nv_bfloat162*)(g_bf + oClz + (size_t)mm*N + n) = ll;
                    }
                }
            }
        }
    }
}

// ---------------- HMMA split-bf16 GEMM 64x64 (for small-N GEMMs) -------------
#define G64_BUF 5120
#define G64_SMEM (8*G64_BUF)

__global__ __launch_bounds__(256) void k_mma_gemm64(
        size_t oAh, size_t oAl, size_t oWh, size_t oWl,
        float* __restrict__ C, int M, int N, int K,
        long sAz, long sWz, long sCz,
        size_t oCh, size_t oCl, int wrBf) {
    const __nv_bfloat16* Ah = g_bf + oAh + (long)blockIdx.z * sAz;
    const __nv_bfloat16* Al = g_bf + oAl + (long)blockIdx.z * sAz;
    const __nv_bfloat16* Wh = g_bf + oWh + (long)blockIdx.z * sWz;
    const __nv_bfloat16* Wl = g_bf + oWl + (long)blockIdx.z * sWz;
    C += (long)blockIdx.z * sCz;
    size_t oChz = oCh + (long)blockIdx.z * sCz;
    size_t oClz = oCl + (long)blockIdx.z * sCz;

    extern __shared__ char gsm[];
    uint32_t aAh = smem_u32(gsm);
    uint32_t aAl = aAh + 2*G64_BUF;
    uint32_t aWh = aAl + 2*G64_BUF;
    uint32_t aWl = aWh + 2*G64_BUF;

    int tid = threadIdx.x;
    int warp = tid >> 5, lane = tid & 31;
    int wm = warp & 1, wn = warp >> 1;
    int m0 = blockIdx.y * 64, n0 = blockIdx.x * 64;

    float acc[2][2][4];
#pragma unroll
    for (int i = 0; i < 2; i++)
#pragma unroll
        for (int j = 0; j < 2; j++)
#pragma unroll
            for (int k = 0; k < 4; k++) acc[i][j][k] = 0.f;

    int a_r = lane & 15, a_k = (lane >> 4) << 3;
    int b_r = ((lane >> 4) & 1)*8 + (lane & 7);
    int b_k = ((lane >> 3) & 1)*8;

    int sr = tid >> 2, sc = (tid & 3) * 8;

    int KT = K / KC;
    {
        uint32_t d = (uint32_t)((sr*SA + sc) * 2);
        cp16(aAh + d, Ah + (size_t)(m0 + sr)*K + sc);
        cp16(aAl + d, Al + (size_t)(m0 + sr)*K + sc);
        cp16(aWh + d, Wh + (size_t)(n0 + sr)*K + sc);
        cp16(aWl + d, Wl + (size_t)(n0 + sr)*K + sc);
        CP_COMMIT();
    }

    int buf = 0;
    for (int c = 0; c < KT; c++) {
        CP_WAIT0();
        __syncthreads();
        if (c + 1 < KT) {
            int k0 = (c + 1) * KC;
            uint32_t o = (uint32_t)((buf ^ 1) * G64_BUF);
            uint32_t d = o + (uint32_t)((sr*SA + sc) * 2);
            cp16(aAh + d, Ah + (size_t)(m0 + sr)*K + k0 + sc);
            cp16(aAl + d, Al + (size_t)(m0 + sr)*K + k0 + sc);
            cp16(aWh + d, Wh + (size_t)(n0 + sr)*K + k0 + sc);
            cp16(aWl + d, Wl + (size_t)(n0 + sr)*K + k0 + sc);
            CP_COMMIT();
        }

        uint32_t bAh = aAh + buf*G64_BUF, bAl = aAl + buf*G64_BUF;
        uint32_t bWh = aWh + buf*G64_BUF, bWl = aWl + buf*G64_BUF;
#pragma unroll
        for (int km = 0; km < 2; km++) {
            uint32_t ah[2][4], al[2][4];
#pragma unroll
            for (int mi = 0; mi < 2; mi++) {
                int off = ((wm*32 + mi*16 + a_r)*SA + km*16 + a_k) * 2;
                ldsm_x4(ah[mi], bAh + off);
                ldsm_x4(al[mi], bAl + off);
            }
            int boff = ((wn*16 + b_r)*SA + km*16 + b_k) * 2;
            uint32_t th[4], tl[4];
            ldsm_x4(th, bWh + boff);
            ldsm_x4(tl, bWl + boff);
            uint32_t bh[2][2] = {{th[0], th[1]}, {th[2], th[3]}};
            uint32_t bl[2][2] = {{tl[0], tl[1]}, {tl[2], tl[3]}};
#pragma unroll
            for (int mi = 0; mi < 2; mi++)
#pragma unroll
                for (int ni = 0; ni < 2; ni++) {
                    mma16816(acc[mi][ni], ah[mi], bh[ni]);
                    mma16816(acc[mi][ni], ah[mi], bl[ni]);
                    mma16816(acc[mi][ni], al[mi], bh[ni]);
                }
        }
        __syncthreads();
        buf ^= 1;
    }

#pragma unroll
    for (int mi = 0; mi < 2; mi++)
#pragma unroll
        for (int ni = 0; ni < 2; ni++)
#pragma unroll
            for (int pe = 0; pe < 2; pe++) {
                int m = m0 + wm*32 + mi*16 + (lane >> 2) + pe*8;
                int n = n0 + wn*16 + ni*8 + (lane & 3)*2;
                float v0 = acc[mi][ni][pe*2+0];
                float v1 = acc[mi][ni][pe*2+1];
                *(float2*)(C + (size_t)m*N + n) = make_float2(v0, v1);
                if (wrBf) {
                    __nv_bfloat16 h0, l0, h1, l1;
                    split2(v0, h0, l0); split2(v1, h1, l1);
                    __nv_bfloat162 hh; hh.x = h0; hh.y = h1;
                    __nv_bfloat162 ll; ll.x = l0; ll.y = l1;
                    *(__nv_bfloat162*)(g_bf + oChz + (size_t)m*N + n) = hh;
                    *(__nv_bfloat162*)(g_bf + oClz + (size_t)m*N + n) = ll;
                }
            }
}

// ---------------- embedding (fp32 + bf16 hi/lo, both dirs) -------------------
__global__ void k_embed(const int* __restrict__ ids, const float* __restrict__ mask,
                        const float* __restrict__ tok, const float* __restrict__ pos) {
    int bl = blockIdx.x;
    int d  = threadIdx.x;
    int b = bl / LSEQ, l = bl % LSEQ;
    int id = ids[bl];
    float v = (tok[(size_t)id*DM + d] + pos[(size_t)l*DM + d]) * mask[bl];
    size_t i0 = (size_t)bl*DM + d;
    size_t i1 = (size_t)M2*DM + ((size_t)b*LSEQ + (LSEQ-1-l))*DM + d;
    g_scratch[OFF_H + i0] = v;
    g_scratch[OFF_H + i1] = v;
    __nv_bfloat16 hb, lb;
    split2(v, hb, lb);
    g_bf[B_ACTH + i0] = hb; g_bf[B_ACTL + i0] = lb;
    g_bf[B_ACTH + i1] = hb; g_bf[B_ACTL + i1] = lb;
}

// ---------------- scan pass 1: fused conv+SiLU + attention-form HMMA scan ----
// smem 55808: sT aliases sB (B dead after Bw^T built via reg staging)
#define SQ 72
#define SCAN_SMEM 55808

__global__ __launch_bounds__(256, 3) void k_scan1(const float* __restrict__ A_log,
                                               const float* __restrict__ Dp,
                                               const float* __restrict__ cw,
                                               const float* __restrict__ cbias,
                                               const float* __restrict__ dtb, int layer) {
    extern __shared__ char sm[];
    __nv_bfloat16* sBh = (__nv_bfloat16*)(sm);
    __nv_bfloat16* sBl = (__nv_bfloat16*)(sm + 9216);
    __nv_bfloat16* sMh = (__nv_bfloat16*)(sm + 18432);
    __nv_bfloat16* sMl = (__nv_bfloat16*)(sm + 27648);
    __nv_bfloat16* sXh = (__nv_bfloat16*)(sm + 36864);
    __nv_bfloat16* sXl = (__nv_bfloat16*)(sm + 46080);
    __nv_bfloat16* sTh = sBh;            // alias: B dead after BwT build
    __nv_bfloat16* sTl = sBl;
    float* sdtr = (float*)(sm + 55296);
    float* sdt  = (float*)(sm + 55552);
    float* sStage = (float*)(sm);

    int idx = blockIdx.x;
    int chunk = idx & 15; idx >>= 4;
    int hh = idx & 7; idx >>= 3;
    int b = idx & 1; int dir = idx >> 1;
    int hg = (dir*2 + b)*8 + hh;
    int tid = threadIdx.x;
    int warp = tid >> 5, lane = tid & 31;
    int li = dir*NLAYERS + layer;
    float Aa = -expf(A_log[li*NH + hh]);
    float Dv = Dp[li*NH + hh];
    const float* zx = g_scratch + OFF_ZX + (size_t)dir*M2*DIP + (size_t)b*LSEQ*DIP;
    float* cc       = g_scratch + OFF_CC + ((size_t)dir*M2 + (size_t)b*LSEQ)*DS;
    float* y        = g_scratch + OFF_Y  + (size_t)dir*M2*DI + (size_t)b*LSEQ*DI;
    float* sdt_g    = g_scratch + OFF_SDT + (size_t)hg*LSEQ;
    int s0 = chunk * QCH;

    // ---- fused conv+SiLU staging: thread owns 4 consecutive rows x 4 chans --
    {
        int cg4 = (tid & 15) * 4;
        int rb = (tid >> 4) * 4;
        float v[7][4];
        float4 wch[4];
        float bch[4];
#pragma unroll
        for (int tns = 0; tns < 3; tns++) {
            int ch = (tns == 0) ? (DI + cg4)
                   : (tns == 1) ? (DI + DS + cg4)
                   : (hh*HD + cg4);
#pragma unroll
            for (int k = 0; k < 7; k++) {
                int ls = s0 + rb - 3 + k;
                if (ls >= 0) {
                    float4 t = *(const float4*)(zx + (size_t)ls*DIP + DI + ch);
                    v[k][0]=t.x; v[k][1]=t.y; v[k][2]=t.z; v[k][3]=t.w;
                } else { v[k][0]=0.f; v[k][1]=0.f; v[k][2]=0.f; v[k][3]=0.f; }
            }
#pragma unroll
            for (int c = 0; c < 4; c++) {
                wch[c] = *(const float4*)(cw + ((size_t)li*CD + ch + c)*4);
                bch[c] = cbias[(size_t)li*CD + ch + c];
            }
#pragma unroll
            for (int j = 0; j < 4; j++) {
                int r = rb + j;
#pragma unroll
                for (int c = 0; c < 4; c++) {
                    float a = v[j][c]*wch[c].x + v[j+1][c]*wch[c].y
                            + v[j+2][c]*wch[c].z + v[j+3][c]*wch[c].w + bch[c];
                    float s = a / (1.f + __expf(-a));
                    __nv_bfloat16 h, l;
                    split2(s, h, l);
                    if (tns == 0) {
                        sBh[r*SQ + cg4 + c] = h; sBl[r*SQ + cg4 + c] = l;
                    } else if (tns == 1) {
                        sMh[r*SQ + cg4 + c] = h; sMl[r*SQ + cg4 + c] = l;
                        if (hh == 0) cc[(size_t)(s0 + r)*DS + cg4 + c] = s;
                    } else {
                        sXh[(cg4 + c)*SQ + r] = h; sXl[(cg4 + c)*SQ + r] = l;
                    }
                }
            }
        }
    }
    if (tid < QCH) {
        float raw = zx[(size_t)(s0 + tid)*DIP + DI + CD + hh] + dtb[li*NH + hh];
        sdtr[tid] = (raw > 20.f) ? raw : log1pf(expf(raw));
    }
    __syncthreads();

    int wm = warp & 1, wn = warp >> 1;
    uint32_t baseBh = smem_u32(sBh), baseBl = smem_u32(sBl);
    uint32_t baseMh = smem_u32(sMh), baseMl = smem_u32(sMl);
    uint32_t baseXh = smem_u32(sXh), baseXl = smem_u32(sXl);
    uint32_t baseTh = baseBh, baseTl = baseBl;
    int a_r = lane & 15, a_k = (lane >> 4) << 3;
    int b_r = ((lane >> 4) & 1)*8 + (lane & 7);
    int b_k = ((lane >> 3) & 1)*8;

    float accG[2][2][4];
#pragma unroll
    for (int mi = 0; mi < 2; mi++)
#pragma unroll
        for (int ni = 0; ni < 2; ni++)
#pragma unroll
            for (int e = 0; e < 4; e++) accG[mi][ni][e] = 0.f;

#pragma unroll
    for (int kk = 0; kk < 4; kk++) {
        uint32_t ah[2][4], al[2][4];
#pragma unroll
        for (int mi = 0; mi < 2; mi++) {
            int off = ((wm*32 + mi*16 + a_r)*SQ + kk*16 + a_k) * 2;
            ldsm_x4(ah[mi], baseMh + off);
            ldsm_x4(al[mi], baseMl + off);
        }
        int boff = ((wn*16 + b_r)*SQ + kk*16 + b_k) * 2;
        uint32_t th[4], tl[4];
        ldsm_x4(th, baseBh + boff);
        ldsm_x4(tl, baseBl + boff);
        uint32_t bh[2][2] = {{th[0], th[1]}, {th[2], th[3]}};
        uint32_t bl[2][2] = {{tl[0], tl[1]}, {tl[2], tl[3]}};
#pragma unroll
        for (int mi = 0; mi < 2; mi++)
#pragma unroll
            for (int ni = 0; ni < 2; ni++) {
                mma16816(accG[mi][ni], ah[mi], bh[ni]);
                mma16816(accG[mi][ni], ah[mi], bl[ni]);
                mma16816(accG[mi][ni], al[mi], bh[ni]);
            }
    }
    __syncthreads();

    if (tid < QCH) {
        float s = sdtr[tid];
#pragma unroll
        for (int o = 1; o < 32; o <<= 1) {
            float t = __shfl_up_sync(0xffffffffu, s, o);
            if ((tid & 31) >= o) s += t;
        }
        sdt[tid] = s;
    }
    __syncthreads();
    if (tid >= 32 && tid < QCH) sdt[tid] += sdt[31];
    __syncthreads();
    float S = sdt[QCH-1];
    if (tid < QCH) sdt_g[s0 + tid] = sdt[tid];
    if (tid == 0) g_scratch[OFF_CSUM + hg*NCHUNK + chunk] = S;

    // ---- build Bw^T into the SAME region as B: read to regs, bar, write ----
    {
        int bi = tid >> 2, nb = (tid & 3) * 16;
        float wv = __expf(Aa * (S - sdt[bi])) * sdtr[bi];
        float fv[16];
#pragma unroll
        for (int n = 0; n < 16; n++) {
            int nn = nb + n;
            fv[n] = wv * (__bfloat162float(sBh[bi*SQ + nn]) + __bfloat162float(sBl[bi*SQ + nn]));
        }
        __syncthreads();   // all B reads done before overwrite
#pragma unroll
        for (int n = 0; n < 16; n++) {
            int nn = nb + n;
            __nv_bfloat16 h, l;
            split2(fv[n], h, l);
            sTh[nn*SQ + bi] = h; sTl[nn*SQ + bi] = l;
        }
    }

#pragma unroll
    for (int mi = 0; mi < 2; mi++)
#pragma unroll
        for (int ni = 0; ni < 2; ni++)
#pragma unroll
            for (int pe = 0; pe < 2; pe++) {
                int j  = wm*32 + mi*16 + (lane >> 2) + pe*8;
                int i0 = wn*16 + ni*8 + (lane & 3)*2;
                float m0v = 0.f, m1v = 0.f;
                if (j >= i0) {
                    m0v = accG[mi][ni][pe*2+0] * __expf(Aa*(sdt[j]-sdt[i0])) * sdtr[i0];
                    if (j == i0) m0v += Dv;
                }
                int i1 = i0 + 1;
                if (j >= i1) {
                    m1v = accG[mi][ni][pe*2+1] * __expf(Aa*(sdt[j]-sdt[i1])) * sdtr[i1];
                    if (j == i1) m1v += Dv;
                }
                __nv_bfloat16 h0, l0, h1, l1;
                split2(m0v, h0, l0); split2(m1v, h1, l1);
                __nv_bfloat162 hh2; hh2.x = h0; hh2.y = h1;
                __nv_bfloat162 ll2; ll2.x = l0; ll2.y = l1;
                *(__nv_bfloat162*)&sMh[j*SQ + i0] = hh2;
                *(__nv_bfloat162*)&sMl[j*SQ + i0] = ll2;
            }
    __syncthreads();

    float accY[2][2][4], accH[2][2][4];
#pragma unroll
    for (int mi = 0; mi < 2; mi++)
#pragma unroll
        for (int ni = 0; ni < 2; ni++)
#pragma unroll
            for (int e = 0; e < 4; e++) { accY[mi][ni][e] = 0.f; accH[mi][ni][e] = 0.f; }

#pragma unroll
    for (int kk = 0; kk < 4; kk++) {
        int boff = ((wn*16 + b_r)*SQ + kk*16 + b_k) * 2;
        uint32_t th[4], tl[4];
        ldsm_x4(th, baseXh + boff);
        ldsm_x4(tl, baseXl + boff);
        uint32_t xh[2][2] = {{th[0], th[1]}, {th[2], th[3]}};
        uint32_t xl[2][2] = {{tl[0], tl[1]}, {tl[2], tl[3]}};
        uint32_t mh[2][4], ml[2][4], hhh[2][4], hll[2][4];
#pragma unroll
        for (int mi = 0; mi < 2; mi++) {
            int off = ((wm*32 + mi*16 + a_r)*SQ + kk*16 + a_k) * 2;
            ldsm_x4(mh[mi], baseMh + off);
            ldsm_x4(ml[mi], baseMl + off);
            ldsm_x4(hhh[mi], baseTh + off);
            ldsm_x4(hll[mi], baseTl + off);
        }
#pragma unroll
        for (int mi = 0; mi < 2; mi++)
#pragma unroll
            for (int ni = 0; ni < 2; ni++) {
                mma16816(accY[mi][ni], mh[mi], xh[ni]);
                mma16816(accY[mi][ni], mh[mi], xl[ni]);
                mma16816(accY[mi][ni], ml[mi], xh[ni]);
                mma16816(accH[mi][ni], hhh[mi], xh[ni]);
                mma16816(accH[mi][ni], hhh[mi], xl[ni]);
                mma16816(accH[mi][ni], hll[mi], xh[ni]);
            }
    }

#pragma unroll
    for (int mi = 0; mi < 2; mi++)
#pragma unroll
        for (int ni = 0; ni < 2; ni++)
#pragma unroll
            for (int pe = 0; pe < 2; pe++) {
                int j = wm*32 + mi*16 + (lane >> 2) + pe*8;
                int p = wn*16 + ni*8 + (lane & 3)*2;
                *(float2*)(y + (size_t)(s0 + j)*DI + hh*HD + p) =
                    make_float2(accY[mi][ni][pe*2+0], accY[mi][ni][pe*2+1]);
            }

    __syncthreads();
#pragma unroll
    for (int mi = 0; mi < 2; mi++)
#pragma unroll
        for (int ni = 0; ni < 2; ni++)
#pragma unroll
            for (int pe = 0; pe < 2; pe++) {
                int n = wm*32 + mi*16 + (lane >> 2) + pe*8;
                int p = wn*16 + ni*8 + (lane & 3)*2;
                *(float2*)&sStage[n*66 + p] =
                    make_float2(accH[mi][ni][pe*2+0], accH[mi][ni][pe*2+1]);
            }
    __syncthreads();
    {
        float* hl = g_scratch + OFF_HLOC + ((size_t)hg*NCHUNK + chunk)*(HD*DS);
        int p = tid >> 2, nb = (tid & 3) * 16;
#pragma unroll
        for (int v2 = 0; v2 < 4; v2++) {
            int n = nb + v2*4;
            float4 o = make_float4(sStage[(n+0)*66 + p], sStage[(n+1)*66 + p],
                                   sStage[(n+2)*66 + p], sStage[(n+3)*66 + p]);
            *(float4*)(hl + (size_t)p*DS + n) = o;
        }
    }
}

// ---------------- scan pass 2: inter-chunk state carry -----------------------
__global__ __launch_bounds__(256) void k_scan2(const float* __restrict__ A_log, int layer) {
    int hg = blockIdx.x >> 4;
    int e  = (blockIdx.x & 15)*256 + threadIdx.x;
    int dir = hg >> 4, hh = hg & 7;
    int li = dir*NLAYERS + layer;
    float Aa = -expf(A_log[li*NH + hh]);
    const float* csum = g_scratch + OFF_CSUM + hg*NCHUNK;
    float* hl = g_scratch + OFF_HLOC + (size_t)hg*NCHUNK*(HD*DS) + e;
    float tmp[NCHUNK];
#pragma unroll
    for (int c = 0; c < NCHUNK; c++) tmp[c] = hl[(size_t)c*(HD*DS)];
    float carry = 0.f;
#pragma unroll
    for (int c = 0; c < NCHUNK; c++) {
        hl[(size_t)c*(HD*DS)] = carry;
        carry = carry * __expf(Aa * csum[c]) + tmp[c];
    }
}

// ---------------- scan pass 3: HMMA correction  y += cum∘(C·H_in) ------------
__global__ __launch_bounds__(256) void k_scan3(const float* __restrict__ A_log, int layer) {
    __shared__ __align__(16) __nv_bfloat16 sCh[64*SQ];
    __shared__ __align__(16) __nv_bfloat16 sCl[64*SQ];
    __shared__ __align__(16) __nv_bfloat16 sHh[64*SQ];
    __shared__ __align__(16) __nv_bfloat16 sHl[64*SQ];
    __shared__ float scum[QCH];

    int idx = blockIdx.x;
    int chunk = idx & 15; idx >>= 4;
    if (chunk == 0) return;
    int hh = idx & 7; idx >>= 3;
    int b = idx & 1; int dir = idx >> 1;
    int hg = (dir*2 + b)*8 + hh;
    int tid = threadIdx.x;
    int warp = tid >> 5, lane = tid & 31;
    int li = dir*NLAYERS + layer;
    float Aa = -expf(A_log[li*NH + hh]);
    const float* cc = g_scratch + OFF_CC + ((size_t)dir*M2 + (size_t)b*LSEQ)*DS;
    float* y        = g_scratch + OFF_Y  + (size_t)dir*M2*DI + (size_t)b*LSEQ*DI;
    const float* sdt_g = g_scratch + OFF_SDT + (size_t)hg*LSEQ;
    const float* hloc  = g_scratch + OFF_HLOC + ((size_t)hg*NCHUNK + chunk)*(HD*DS);
    int s0 = chunk * QCH;

#pragma unroll
    for (int i = 0; i < 4; i++) {
        int id = tid + i*256;
        int r = id >> 4, c4 = (id & 15) * 4;
        float4 cv = *(const float4*)(cc + (size_t)(s0 + r)*DS + c4);
        float4 hv = *(const float4*)(hloc + (size_t)r*DS + c4);
        float ccv[4] = {cv.x, cv.y, cv.z, cv.w};
        float hhv[4] = {hv.x, hv.y, hv.z, hv.w};
#pragma unroll
        for (int k = 0; k < 4; k++) {
            __nv_bfloat16 h, l;
            split2(ccv[k], h, l);
            sCh[r*SQ + c4 + k] = h; sCl[r*SQ + c4 + k] = l;
            split2(hhv[k], h, l);
            sHh[r*SQ + c4 + k] = h; sHl[r*SQ + c4 + k] = l;
        }
    }
    if (tid < QCH) scum[tid] = __expf(Aa * sdt_g[s0 + tid]);
    __syncthreads();

    int wm = warp & 1, wn = warp >> 1;
    uint32_t baseCh = smem_u32(sCh), baseCl = smem_u32(sCl);
    uint32_t baseHh = smem_u32(sHh), baseHl = smem_u32(sHl);
    int a_r = lane & 15, a_k = (lane >> 4) << 3;
    int b_r = ((lane >> 4) & 1)*8 + (lane & 7);
    int b_k = ((lane >> 3) & 1)*8;

    float accY[2][2][4];
#pragma unroll
    for (int mi = 0; mi < 2; mi++)
#pragma unroll
        for (int ni = 0; ni < 2; ni++)
#pragma unroll
            for (int e = 0; e < 4; e++) accY[mi][ni][e] = 0.f;

#pragma unroll
    for (int kk = 0; kk < 4; kk++) {
        uint32_t ah[2][4], al[2][4];
#pragma unroll
        for (int mi = 0; mi < 2; mi++) {
            int off = ((wm*32 + mi*16 + a_r)*SQ + kk*16 + a_k) * 2;
            ldsm_x4(ah[mi], baseCh + off);
            ldsm_x4(al[mi], baseCl + off);
        }
        int boff = ((wn*16 + b_r)*SQ + kk*16 + b_k) * 2;
        uint32_t th[4], tl[4];
        ldsm_x4(th, baseHh + boff);
        ldsm_x4(tl, baseHl + boff);
        uint32_t bh[2][2] = {{th[0], th[1]}, {th[2], th[3]}};
        uint32_t bl[2][2] = {{tl[0], tl[1]}, {tl[2], tl[3]}};
#pragma unroll
        for (int mi = 0; mi < 2; mi++)
#pragma unroll
            for (int ni = 0; ni < 2; ni++) {
                mma16816(accY[mi][ni], ah[mi], bh[ni]);
                mma16816(accY[mi][ni], ah[mi], bl[ni]);
                mma16816(accY[mi][ni], al[mi], bh[ni]);
            }
    }

#pragma unroll
    for (int mi = 0; mi < 2; mi++)
#pragma unroll
        for (int ni = 0; ni < 2; ni++)
#pragma unroll
            for (int pe = 0; pe < 2; pe++) {
                int j = wm*32 + mi*16 + (lane >> 2) + pe*8;
                int p = wn*16 + ni*8 + (lane & 3)*2;
                float cum = scum[j];
                float* yp = y + (size_t)(s0 + j)*DI + hh*HD + p;
                float2 old = *(float2*)yp;
                old.x += cum * accY[mi][ni][pe*2+0];
                old.y += cum * accY[mi][ni][pe*2+1];
                *(float2*)yp = old;
            }
}

// ---------------- gated RMSNorm (writes bf16 hi/lo for out_proj) -------------
__global__ __launch_bounds__(512) void k_gatedrms(const float* __restrict__ nw, int layer) {
    int dir = blockIdx.y;
    int m = blockIdx.x;
    int i = threadIdx.x;
    int li = dir*NLAYERS + layer;
    float yv = g_scratch[OFF_Y + (size_t)dir*M2*DI + (size_t)m*DI + i];
    float zv = g_scratch[OFF_ZX + (size_t)dir*M2*DIP + (size_t)m*DIP + i];
    float g = yv * (zv / (1.f + __expf(-zv)));
    float ss = g * g;
#pragma unroll
    for (int o = 16; o > 0; o >>= 1) ss += __shfl_xor_sync(0xffffffffu, ss, o);
    __shared__ float red[16];
    if ((i & 31) == 0) red[i >> 5] = ss;
    __syncthreads();
    if (i < 32) {
        float v = (i < 16) ? red[i] : 0.f;
#pragma unroll
        for (int o = 8; o > 0; o >>= 1) v += __shfl_xor_sync(0xffffffffu, v, o);
        if (i == 0) red[0] = v;
    }
    __syncthreads();
    float inv = rsqrtf(red[0] * (1.f/DI) + 1e-5f);
    float o = g * inv * nw[(size_t)li*DI + i];
    size_t oi = (size_t)dir*M2*DI + (size_t)m*DI + i;
    __nv_bfloat16 hb, lb;
    split2(o, hb, lb);
    g_bf[B_NRMH + oi] = hb;
    g_bf[B_NRML + oi] = lb;
}

// ---------------- combine fwd + flipped bwd (bf16 hi/lo) ---------------------
__global__ void k_comb() {
    int m = blockIdx.x;
    int i = threadIdx.x;
    int b = m / LSEQ, l = m % LSEQ;
    float v;
    if (i < DM) v = g_scratch[OFF_H + (size_t)m*DM + i];
    else        v = g_scratch[OFF_H + (size_t)M2*DM + ((size_t)b*LSEQ + (LSEQ-1-l))*DM + (i-DM)];
    size_t oi = (size_t)m*2*DM + i;
    __nv_bfloat16 hb, lb;
    split2(v, hb, lb);
    g_bf[B_COMBH + oi] = hb;
    g_bf[B_COMBL + oi] = lb;
}

// ---------------- gate sigmoid + fuse + LayerNorm ---------------------------
__global__ __launch_bounds__(256) void k_final(const float* __restrict__ fb,
                                               const float* __restrict__ lnw,
                                               const float* __restrict__ lnb,
                                               float* __restrict__ out) {
    int m = blockIdx.x;
    int d = threadIdx.x;
    int b = m / LSEQ, l = m % LSEQ;
    float gl0 = g_scratch[OFF_GATE + (size_t)m*2*DM + d] + fb[d];
    float gl1 = g_scratch[OFF_GATE + (size_t)m*2*DM + DM + d] + fb[DM + d];
    float gf = 1.f / (1.f + __expf(-gl0));
    float gb = 1.f / (1.f + __expf(-gl1));
    float fwd = g_scratch[OFF_H + (size_t)m*DM + d];
    float bwd = g_scratch[OFF_H + (size_t)M2*DM + ((size_t)b*LSEQ + (LSEQ-1-l))*DM + d];
    float fu = gf*fwd + gb*bwd;

    float s1 = fu, s2 = fu*fu;
#pragma unroll
    for (int o = 16; o > 0; o >>= 1) {
        s1 += __shfl_xor_sync(0xffffffffu, s1, o);
        s2 += __shfl_xor_sync(0xffffffffu, s2, o);
    }
    __shared__ float r1[8], r2[8];
    if ((d & 31) == 0) { r1[d >> 5] = s1; r2[d >> 5] = s2; }
    __syncthreads();
    if (d < 32) {
        float v1 = (d < 8) ? r1[d] : 0.f;
        float v2 = (d < 8) ? r2[d] : 0.f;
#pragma unroll
        for (int o = 4; o > 0; o >>= 1) {
            v1 += __shfl_xor_sync(0xffffffffu, v1, o);
            v2 += __shfl_xor_sync(0xffffffffu, v2, o);
        }
        if (d == 0) { r1[0] = v1; r2[0] = v2; }
    }
    __syncthreads();
    float mu = r1[0] * (1.f/DM);
    float var = r2[0] * (1.f/DM) - mu*mu;
    float inv = rsqrtf(var + 1e-5f);
    out[(size_t)m*DM + d] = (fu - mu) * inv * lnw[d] + lnb[d];
}

// ---------------------------------------------------------------------------
extern "C" void kernel_launch(void* const* d_in, const int* in_sizes, int n_in,
                              void* d_out, int out_size) {
    const int*   ids  = (const int*)d_in[0];
    const float* mask = (const float*)d_in[1];
    const float* tok  = (const float*)d_in[2];
    const float* pos  = (const float*)d_in[3];
    const float* inw  = (const float*)d_in[4];
    const float* cw   = (const float*)d_in[5];
    const float* cb   = (const float*)d_in[6];
    const float* dtb  = (const float*)d_in[7];
    const float* alog = (const float*)d_in[8];
    const float* dpar = (const float*)d_in[9];
    const float* nw   = (const float*)d_in[10];
    const float* ow   = (const float*)d_in[11];
    const float* fw   = (const float*)d_in[12];
    const float* fb   = (const float*)d_in[13];
    const float* lnw  = (const float*)d_in[14];
    const float* lnb  = (const float*)d_in[15];

    cudaFuncSetAttribute(k_scan1, cudaFuncAttributeMaxDynamicSharedMemorySize, SCAN_SMEM);
    cudaFuncSetAttribute(k_mma_gemm, cudaFuncAttributeMaxDynamicSharedMemorySize, GEMM_SMEM);
    cudaFuncSetAttribute(k_mma_gemm64, cudaFuncAttributeMaxDynamicSharedMemorySize, G64_SMEM);

    float* scr = nullptr;
    cudaGetSymbolAddress((void**)&scr, g_scratch);
    float* pH    = scr + OFF_H;
    float* pZX   = scr + OFF_ZX;
    float* pGATE = scr + OFF_GATE;

    {
        int n1 = 2*NLAYERS*DIP*DM;
        int n2 = 2*NLAYERS*DM*DI;
        int n3 = (2*DM)*(2*DM);
        int tot = n1 + n2 + n3;
        k_cvt3<<<(tot/4 + 255)/256, 256>>>(inw, n1, ow, n2, fw, n3);
    }

    k_embed<<<M2, DM>>>(ids, mask, tok, pos);

    for (int layer = 0; layer < NLAYERS; layer++) {
        k_mma_gemm<<<dim3((DIP + 63)/64, M2/128, 2), 256, GEMM_SMEM>>>(
            B_ACTH, B_ACTL,
            B_WINH + (size_t)layer*DIP*DM, B_WINL + (size_t)layer*DIP*DM,
            pZX, M2, DIP, DM,
            (long)M2*DM, (long)NLAYERS*DIP*DM, (long)M2*DIP,
            0, 0, 0);
        k_scan1<<<512, 256, SCAN_SMEM>>>(alog, dpar, cw, cb, dtb, layer);
        k_scan2<<<512, 256>>>(alog, layer);
        k_scan3<<<512, 256>>>(alog, layer);
        k_gatedrms<<<dim3(M2, 2), DI>>>(nw, layer);
        int wrBf = (layer + 1 < NLAYERS) ? 1 : 0;
        k_mma_gemm64<<<dim3(DM/64, M2/64, 2), 256, G64_SMEM>>>(
            B_NRMH, B_NRML,
            B_WOUTH + (size_t)layer*DM*DI, B_WOUTL + (size_t)layer*DM*DI,
            pH, M2, DM, DI,
            (long)M2*DI, (long)NLAYERS*DM*DI, (long)M2*DM,
            B_ACTH, B_ACTL, wrBf);
    }

    k_comb<<<M2, 2*DM>>>();
    k_mma_gemm64<<<dim3(2*DM/64, M2/64, 1), 256, G64_SMEM>>>(
        B_COMBH, B_COMBL, B_WFUSH, B_WFUSL,
        pGATE, M2, 2*DM, 2*DM, 0, 0, 0,
        0, 0, 0);
    k_final<<<M2, DM>>>(fb, lnw, lnb, (float*)d_out);
}

// round 16
// speedup vs baseline: 1.0154x; 1.0154x over previous
#include <cuda_runtime.h>
#include <cuda_bf16.h>
#include <math.h>
#include <cstdint>

#define BB 2
#define LSEQ 1024
#define DM 256
#define DI 512
#define DS 64
#define NH 8
#define HD 64
#define CD 640
#define DIP 1160
#define M2 (BB*LSEQ)
#define NLAYERS 2
#define NCHUNK 16
#define QCH 64

// ------------------------- fp32 scratch -------------------------------------
static constexpr size_t OFF_H    = 0;
static constexpr size_t OFF_ZX   = OFF_H    + (size_t)2*M2*DM;
static constexpr size_t OFF_BC   = OFF_ZX   + (size_t)2*M2*DIP;   // conv(B,C): [dir][bl][128]
static constexpr size_t OFF_DTB  = OFF_BC   + (size_t)2*M2*128;   // softplus dt: [dir][bl][8]
static constexpr size_t OFF_Y    = OFF_DTB  + (size_t)2*M2*NH;
static constexpr size_t OFF_GATE = OFF_Y    + (size_t)2*M2*DI;
static constexpr size_t OFF_HLOC = OFF_GATE + (size_t)M2*2*DM;
static constexpr size_t OFF_SDT  = OFF_HLOC + (size_t)32*NCHUNK*HD*DS;
static constexpr size_t OFF_CSUM = OFF_SDT  + (size_t)32*LSEQ;
static constexpr size_t SCRATCH_TOTAL = OFF_CSUM + (size_t)32*NCHUNK;

__device__ float g_scratch[SCRATCH_TOTAL];

// ------------------------- bf16 hi/lo scratch -------------------------------
static constexpr size_t B_ACTH  = 0;
static constexpr size_t B_ACTL  = B_ACTH  + (size_t)2*M2*DM;
static constexpr size_t B_NRMH  = B_ACTL  + (size_t)2*M2*DM;
static constexpr size_t B_NRML  = B_NRMH  + (size_t)2*M2*DI;
static constexpr size_t B_COMBH = B_NRML  + (size_t)2*M2*DI;
static constexpr size_t B_COMBL = B_COMBH + (size_t)M2*2*DM;
static constexpr size_t B_WINH  = B_COMBL + (size_t)M2*2*DM;
static constexpr size_t B_WINL  = B_WINH  + (size_t)2*NLAYERS*DIP*DM;
static constexpr size_t B_WOUTH = B_WINL  + (size_t)2*NLAYERS*DIP*DM;
static constexpr size_t B_WOUTL = B_WOUTH + (size_t)2*NLAYERS*DM*DI;
static constexpr size_t B_WFUSH = B_WOUTL + (size_t)2*NLAYERS*DM*DI;
static constexpr size_t B_WFUSL = B_WFUSH + (size_t)(2*DM)*(2*DM);
static constexpr size_t BF_TOTAL = B_WFUSL + (size_t)(2*DM)*(2*DM);

__device__ __align__(16) __nv_bfloat16 g_bf[BF_TOTAL];

typedef unsigned long long ull;

// ---- HMMA helpers -----------------------------------------------------------
__device__ __forceinline__ uint32_t smem_u32(const void* p) {
    uint32_t a;
    asm("{ .reg .u64 t; cvta.to.shared.u64 t, %1; cvt.u32.u64 %0, t; }" : "=r"(a) : "l"(p));
    return a;
}
__device__ __forceinline__ void ldsm_x4(uint32_t* r, uint32_t addr) {
    asm volatile("ldmatrix.sync.aligned.m8n8.x4.shared.b16 {%0,%1,%2,%3}, [%4];"
        : "=r"(r[0]), "=r"(r[1]), "=r"(r[2]), "=r"(r[3]) : "r"(addr));
}
__device__ __forceinline__ void mma16816(float* d, const uint32_t* a, const uint32_t* b) {
    asm volatile("mma.sync.aligned.m16n8k16.row.col.f32.bf16.bf16.f32 "
        "{%0,%1,%2,%3}, {%4,%5,%6,%7}, {%8,%9}, {%0,%1,%2,%3};"
        : "+f"(d[0]), "+f"(d[1]), "+f"(d[2]), "+f"(d[3])
        : "r"(a[0]), "r"(a[1]), "r"(a[2]), "r"(a[3]), "r"(b[0]), "r"(b[1]));
}
__device__ __forceinline__ void split2(float v, __nv_bfloat16& h, __nv_bfloat16& l) {
    h = __float2bfloat16(v);
    l = __float2bfloat16(v - __bfloat162float(h));
}
__device__ __forceinline__ void cp16(uint32_t d, const void* s) {
    asm volatile("cp.async.ca.shared.global [%0], [%1], 16;" :: "r"(d), "l"(s));
}
__device__ __forceinline__ void cp16z(uint32_t d, const void* s, int sz) {
    asm volatile("cp.async.ca.shared.global [%0], [%1], 16, %2;" :: "r"(d), "l"(s), "r"(sz));
}
#define CP_COMMIT() asm volatile("cp.async.commit_group;" ::: "memory")
#define CP_WAIT0()  asm volatile("cp.async.wait_group 0;" ::: "memory")

// ---------------- fused fp32 -> bf16 hi/lo conversion (3 weight arrays) ------
__global__ void k_cvt3(const float* __restrict__ w1, int n1,
                       const float* __restrict__ w2, int n2,
                       const float* __restrict__ w3, int n3) {
    int i = (blockIdx.x*blockDim.x + threadIdx.x)*4;
    const float* x; size_t oh, ol; int base;
    if (i < n1)            { x = w1; oh = B_WINH;  ol = B_WINL;  base = 0; }
    else if (i < n1 + n2)  { x = w2; oh = B_WOUTH; ol = B_WOUTL; base = n1; }
    else if (i < n1+n2+n3) { x = w3; oh = B_WFUSH; ol = B_WFUSL; base = n1 + n2; }
    else return;
    int ii = i - base;
    float4 v = *(const float4*)(x + ii);
    float vv[4] = {v.x, v.y, v.z, v.w};
#pragma unroll
    for (int k = 0; k < 4; k++) {
        __nv_bfloat16 h, l;
        split2(vv[k], h, l);
        g_bf[oh + ii + k] = h;
        g_bf[ol + ii + k] = l;
    }
}

// ---------------- HMMA split-bf16 GEMM 128x64, cp.async double-buffered ------
#define KC 32
#define SA 40
#define GA_BUF 10240
#define GW_BUF 5120
#define GEMM_SMEM (2*GA_BUF*2 + 2*GW_BUF*2)

__global__ __launch_bounds__(256) void k_mma_gemm(
        size_t oAh, size_t oAl, size_t oWh, size_t oWl,
        float* __restrict__ C, int M, int N, int K,
        long sAz, long sWz, long sCz,
        size_t oCh, size_t oCl, int wrBf) {
    const __nv_bfloat16* Ah = g_bf + oAh + (long)blockIdx.z * sAz;
    const __nv_bfloat16* Al = g_bf + oAl + (long)blockIdx.z * sAz;
    const __nv_bfloat16* Wh = g_bf + oWh + (long)blockIdx.z * sWz;
    const __nv_bfloat16* Wl = g_bf + oWl + (long)blockIdx.z * sWz;
    C += (long)blockIdx.z * sCz;
    size_t oChz = oCh + (long)blockIdx.z * sCz;
    size_t oClz = oCl + (long)blockIdx.z * sCz;

    extern __shared__ char gsm[];
    uint32_t aAh = smem_u32(gsm);
    uint32_t aAl = aAh + 2*GA_BUF;
    uint32_t aWh = aAl + 2*GA_BUF;
    uint32_t aWl = aWh + 2*GW_BUF;

    int tid = threadIdx.x;
    int warp = tid >> 5, lane = tid & 31;
    int wm = warp & 3, wn = warp >> 2;
    int m0 = blockIdx.y * 128, n0 = blockIdx.x * 64;

    float acc[2][4][4];
#pragma unroll
    for (int i = 0; i < 2; i++)
#pragma unroll
        for (int j = 0; j < 4; j++)
#pragma unroll
            for (int k = 0; k < 4; k++) acc[i][j][k] = 0.f;

    int a_r  = (lane & 15);
    int a_k  = (lane >> 4) << 3;

    int srA = tid >> 2, scA = (tid & 3) * 8;
    int srW = tid >> 2, scW = (tid & 3) * 8;
    int wrow = n0 + srW;
    int wsz = (wrow < N) ? 16 : 0;
    int wclamp = (wrow < N) ? wrow : (N - 1);

    int KT = K / KC;

    {
        int k0 = 0;
#pragma unroll
        for (int i = 0; i < 2; i++) {
            int r = srA + i*64;
            uint32_t d = (uint32_t)((r*SA + scA) * 2);
            cp16(aAh + d, Ah + (size_t)(m0 + r)*K + k0 + scA);
            cp16(aAl + d, Al + (size_t)(m0 + r)*K + k0 + scA);
        }
        uint32_t d = (uint32_t)((srW*SA + scW) * 2);
        cp16z(aWh + d, Wh + (size_t)wclamp*K + k0 + scW, wsz);
        cp16z(aWl + d, Wl + (size_t)wclamp*K + k0 + scW, wsz);
        CP_COMMIT();
    }

    int buf = 0;
    for (int c = 0; c < KT; c++) {
        CP_WAIT0();
        __syncthreads();
        if (c + 1 < KT) {
            int k0 = (c + 1) * KC;
            uint32_t oA = (uint32_t)((buf ^ 1) * GA_BUF);
            uint32_t oW = (uint32_t)((buf ^ 1) * GW_BUF);
#pragma unroll
            for (int i = 0; i < 2; i++) {
                int r = srA + i*64;
                uint32_t d = oA + (uint32_t)((r*SA + scA) * 2);
                cp16(aAh + d, Ah + (size_t)(m0 + r)*K + k0 + scA);
                cp16(aAl + d, Al + (size_t)(m0 + r)*K + k0 + scA);
            }
            uint32_t d = oW + (uint32_t)((srW*SA + scW) * 2);
            cp16z(aWh + d, Wh + (size_t)wclamp*K + k0 + scW, wsz);
            cp16z(aWl + d, Wl + (size_t)wclamp*K + k0 + scW, wsz);
            CP_COMMIT();
        }

        uint32_t bAh = aAh + buf*GA_BUF, bAl = aAl + buf*GA_BUF;
        uint32_t bWh = aWh + buf*GW_BUF, bWl = aWl + buf*GW_BUF;
#pragma unroll
        for (int km = 0; km < 2; km++) {
            uint32_t ah[2][4], al[2][4], bh[4][2], bl[4][2];
#pragma unroll
            for (int mi = 0; mi < 2; mi++) {
                int off = ((wm*32 + mi*16 + a_r)*SA + km*16 + a_k) * 2;
                ldsm_x4(ah[mi], bAh + off);
                ldsm_x4(al[mi], bAl + off);
            }
#pragma unroll
            for (int np = 0; np < 2; np++) {
                int row = wn*32 + (np*2 + ((lane >> 4) & 1))*8 + (lane & 7);
                int off = (row*SA + km*16 + ((lane >> 3) & 1) * 8) * 2;
                uint32_t t4[4];
                ldsm_x4(t4, bWh + off);
                bh[np*2][0] = t4[0]; bh[np*2][1] = t4[1];
                bh[np*2+1][0] = t4[2]; bh[np*2+1][1] = t4[3];
                ldsm_x4(t4, bWl + off);
                bl[np*2][0] = t4[0]; bl[np*2][1] = t4[1];
                bl[np*2+1][0] = t4[2]; bl[np*2+1][1] = t4[3];
            }
#pragma unroll
            for (int mi = 0; mi < 2; mi++)
#pragma unroll
                for (int ni = 0; ni < 4; ni++) {
                    mma16816(acc[mi][ni], ah[mi], bh[ni]);
                    mma16816(acc[mi][ni], ah[mi], bl[ni]);
                    mma16816(acc[mi][ni], al[mi], bh[ni]);
                }
        }
        __syncthreads();
        buf ^= 1;
    }

#pragma unroll
    for (int mi = 0; mi < 2; mi++) {
#pragma unroll
        for (int ni = 0; ni < 4; ni++) {
            int m = m0 + wm*32 + mi*16 + (lane >> 2);
            int n = n0 + wn*32 + ni*8 + (lane & 3)*2;
            if (n < N) {
#pragma unroll
                for (int hrow = 0; hrow < 2; hrow++) {
                    int mm = m + hrow*8;
                    float v0 = acc[mi][ni][hrow*2 + 0];
                    float v1 = acc[mi][ni][hrow*2 + 1];
                    *(float2*)(C + (size_t)mm*N + n) = make_float2(v0, v1);
                    if (wrBf) {
                        __nv_bfloat16 h0, l0, h1, l1;
                        split2(v0, h0, l0); split2(v1, h1, l1);
                        __nv_bfloat162 hh; hh.x = h0; hh.y = h1;
                        __nv_bfloat162 ll; ll.x = l0; ll.y = l1;
                        *(__nv_bfloat162*)(g_bf + oChz + (size_t)mm*N + n) = hh;
                        *(__nv_bfloat162*)(g_bf + oClz + (size_t)mm*N + n) = ll;
                    }
                }
            }
        }
    }
}

// ---------------- HMMA split-bf16 GEMM 64x64 (for small-N GEMMs) -------------
#define G64_BUF 5120
#define G64_SMEM (8*G64_BUF)

__global__ __launch_bounds__(256) void k_mma_gemm64(
        size_t oAh, size_t oAl, size_t oWh, size_t oWl,
        float* __restrict__ C, int M, int N, int K,
        long sAz, long sWz, long sCz,
        size_t oCh, size_t oCl, int wrBf) {
    const __nv_bfloat16* Ah = g_bf + oAh + (long)blockIdx.z * sAz;
    const __nv_bfloat16* Al = g_bf + oAl + (long)blockIdx.z * sAz;
    const __nv_bfloat16* Wh = g_bf + oWh + (long)blockIdx.z * sWz;
    const __nv_bfloat16* Wl = g_bf + oWl + (long)blockIdx.z * sWz;
    C += (long)blockIdx.z * sCz;
    size_t oChz = oCh + (long)blockIdx.z * sCz;
    size_t oClz = oCl + (long)blockIdx.z * sCz;

    extern __shared__ char gsm[];
    uint32_t aAh = smem_u32(gsm);
    uint32_t aAl = aAh + 2*G64_BUF;
    uint32_t aWh = aAl + 2*G64_BUF;
    uint32_t aWl = aWh + 2*G64_BUF;

    int tid = threadIdx.x;
    int warp = tid >> 5, lane = tid & 31;
    int wm = warp & 1, wn = warp >> 1;
    int m0 = blockIdx.y * 64, n0 = blockIdx.x * 64;

    float acc[2][2][4];
#pragma unroll
    for (int i = 0; i < 2; i++)
#pragma unroll
        for (int j = 0; j < 2; j++)
#pragma unroll
            for (int k = 0; k < 4; k++) acc[i][j][k] = 0.f;

    int a_r = lane & 15, a_k = (lane >> 4) << 3;
    int b_r = ((lane >> 4) & 1)*8 + (lane & 7);
    int b_k = ((lane >> 3) & 1)*8;

    int sr = tid >> 2, sc = (tid & 3) * 8;

    int KT = K / KC;
    {
        uint32_t d = (uint32_t)((sr*SA + sc) * 2);
        cp16(aAh + d, Ah + (size_t)(m0 + sr)*K + sc);
        cp16(aAl + d, Al + (size_t)(m0 + sr)*K + sc);
        cp16(aWh + d, Wh + (size_t)(n0 + sr)*K + sc);
        cp16(aWl + d, Wl + (size_t)(n0 + sr)*K + sc);
        CP_COMMIT();
    }

    int buf = 0;
    for (int c = 0; c < KT; c++) {
        CP_WAIT0();
        __syncthreads();
        if (c + 1 < KT) {
            int k0 = (c + 1) * KC;
            uint32_t o = (uint32_t)((buf ^ 1) * G64_BUF);
            uint32_t d = o + (uint32_t)((sr*SA + sc) * 2);
            cp16(aAh + d, Ah + (size_t)(m0 + sr)*K + k0 + sc);
            cp16(aAl + d, Al + (size_t)(m0 + sr)*K + k0 + sc);
            cp16(aWh + d, Wh + (size_t)(n0 + sr)*K + k0 + sc);
            cp16(aWl + d, Wl + (size_t)(n0 + sr)*K + k0 + sc);
            CP_COMMIT();
        }

        uint32_t bAh = aAh + buf*G64_BUF, bAl = aAl + buf*G64_BUF;
        uint32_t bWh = aWh + buf*G64_BUF, bWl = aWl + buf*G64_BUF;
#pragma unroll
        for (int km = 0; km < 2; km++) {
            uint32_t ah[2][4], al[2][4];
#pragma unroll
            for (int mi = 0; mi < 2; mi++) {
                int off = ((wm*32 + mi*16 + a_r)*SA + km*16 + a_k) * 2;
                ldsm_x4(ah[mi], bAh + off);
                ldsm_x4(al[mi], bAl + off);
            }
            int boff = ((wn*16 + b_r)*SA + km*16 + b_k) * 2;
            uint32_t th[4], tl[4];
            ldsm_x4(th, bWh + boff);
            ldsm_x4(tl, bWl + boff);
            uint32_t bh[2][2] = {{th[0], th[1]}, {th[2], th[3]}};
            uint32_t bl[2][2] = {{tl[0], tl[1]}, {tl[2], tl[3]}};
#pragma unroll
            for (int mi = 0; mi < 2; mi++)
#pragma unroll
                for (int ni = 0; ni < 2; ni++) {
                    mma16816(acc[mi][ni], ah[mi], bh[ni]);
                    mma16816(acc[mi][ni], ah[mi], bl[ni]);
                    mma16816(acc[mi][ni], al[mi], bh[ni]);
                }
        }
        __syncthreads();
        buf ^= 1;
    }

#pragma unroll
    for (int mi = 0; mi < 2; mi++)
#pragma unroll
        for (int ni = 0; ni < 2; ni++)
#pragma unroll
            for (int pe = 0; pe < 2; pe++) {
                int m = m0 + wm*32 + mi*16 + (lane >> 2) + pe*8;
                int n = n0 + wn*16 + ni*8 + (lane & 3)*2;
                float v0 = acc[mi][ni][pe*2+0];
                float v1 = acc[mi][ni][pe*2+1];
                *(float2*)(C + (size_t)m*N + n) = make_float2(v0, v1);
                if (wrBf) {
                    __nv_bfloat16 h0, l0, h1, l1;
                    split2(v0, h0, l0); split2(v1, h1, l1);
                    __nv_bfloat162 hh; hh.x = h0; hh.y = h1;
                    __nv_bfloat162 ll; ll.x = l0; ll.y = l1;
                    *(__nv_bfloat162*)(g_bf + oChz + (size_t)m*N + n) = hh;
                    *(__nv_bfloat162*)(g_bf + oClz + (size_t)m*N + n) = ll;
                }
            }
}

// ---------------- embedding (fp32 + bf16 hi/lo, both dirs) -------------------
__global__ void k_embed(const int* __restrict__ ids, const float* __restrict__ mask,
                        const float* __restrict__ tok, const float* __restrict__ pos) {
    int bl = blockIdx.x;
    int d  = threadIdx.x;
    int b = bl / LSEQ, l = bl % LSEQ;
    int id = ids[bl];
    float v = (tok[(size_t)id*DM + d] + pos[(size_t)l*DM + d]) * mask[bl];
    size_t i0 = (size_t)bl*DM + d;
    size_t i1 = (size_t)M2*DM + ((size_t)b*LSEQ + (LSEQ-1-l))*DM + d;
    g_scratch[OFF_H + i0] = v;
    g_scratch[OFF_H + i1] = v;
    __nv_bfloat16 hb, lb;
    split2(v, hb, lb);
    g_bf[B_ACTH + i0] = hb; g_bf[B_ACTL + i0] = lb;
    g_bf[B_ACTH + i1] = hb; g_bf[B_ACTL + i1] = lb;
}

// ---------------- conv+SiLU for B/C channels + dt softplus (shared by heads) -
__global__ __launch_bounds__(128) void k_convbc(const float* __restrict__ cw,
                                                const float* __restrict__ cbias,
                                                const float* __restrict__ dt_bias,
                                                int layer) {
    int dir = blockIdx.y;
    int bl = blockIdx.x;
    int b = bl / LSEQ, l = bl % LSEQ;
    int c = threadIdx.x;               // 0..127 -> conv channel DI + c
    int li = dir*NLAYERS + layer;
    const float* zx = g_scratch + OFF_ZX + (size_t)dir*M2*DIP;
    int ch = DI + c;                   // conv-channel index
    float4 w = *(const float4*)(cw + ((size_t)li*CD + ch)*4);
    float acc = cbias[(size_t)li*CD + ch];
#pragma unroll
    for (int k = 0; k < 4; k++) {
        int ls = l - 3 + k;
        if (ls >= 0)
            acc += zx[((size_t)b*LSEQ + ls)*DIP + DI + ch] * ((const float*)&w)[k];
    }
    float s = acc / (1.f + __expf(-acc));
    g_scratch[OFF_BC + ((size_t)dir*M2 + bl)*128 + c] = s;
    if (c < NH) {
        float raw = zx[(size_t)bl*DIP + DI + CD + c] + dt_bias[li*NH + c];
        float sp = (raw > 20.f) ? raw : log1pf(expf(raw));
        g_scratch[OFF_DTB + ((size_t)dir*M2 + bl)*NH + c] = sp;
    }
}

// ---------------- scan pass 1: x-conv fused + attention-form HMMA scan -------
#define SQ 72
#define SCAN_SMEM 55808

__global__ __launch_bounds__(256, 3) void k_scan1(const float* __restrict__ A_log,
                                               const float* __restrict__ Dp,
                                               const float* __restrict__ cw,
                                               const float* __restrict__ cbias,
                                               int layer) {
    extern __shared__ char sm[];
    __nv_bfloat16* sBh = (__nv_bfloat16*)(sm);
    __nv_bfloat16* sBl = (__nv_bfloat16*)(sm + 9216);
    __nv_bfloat16* sMh = (__nv_bfloat16*)(sm + 18432);
    __nv_bfloat16* sMl = (__nv_bfloat16*)(sm + 27648);
    __nv_bfloat16* sXh = (__nv_bfloat16*)(sm + 36864);
    __nv_bfloat16* sXl = (__nv_bfloat16*)(sm + 46080);
    __nv_bfloat16* sTh = sBh;            // alias: B dead after BwT build
    __nv_bfloat16* sTl = sBl;
    float* sdtr = (float*)(sm + 55296);
    float* sdt  = (float*)(sm + 55552);
    float* sStage = (float*)(sm);

    int idx = blockIdx.x;
    int chunk = idx & 15; idx >>= 4;
    int hh = idx & 7; idx >>= 3;
    int b = idx & 1; int dir = idx >> 1;
    int hg = (dir*2 + b)*8 + hh;
    int tid = threadIdx.x;
    int warp = tid >> 5, lane = tid & 31;
    int li = dir*NLAYERS + layer;
    float Aa = -expf(A_log[li*NH + hh]);
    float Dv = Dp[li*NH + hh];
    const float* zx  = g_scratch + OFF_ZX  + (size_t)dir*M2*DIP + (size_t)b*LSEQ*DIP;
    const float* bc  = g_scratch + OFF_BC  + ((size_t)dir*M2 + (size_t)b*LSEQ)*128;
    const float* dtp = g_scratch + OFF_DTB + ((size_t)dir*M2 + (size_t)b*LSEQ)*NH;
    float* y         = g_scratch + OFF_Y   + (size_t)dir*M2*DI + (size_t)b*LSEQ*DI;
    float* sdt_g     = g_scratch + OFF_SDT + (size_t)hg*LSEQ;
    int s0 = chunk * QCH;

    // ---- stage B, C from precomputed buffer (plain loads + split) -----------
#pragma unroll
    for (int i = 0; i < 8; i++) {
        int id = tid + i*256;
        int r = id >> 5, q = id & 31;
        int c4 = q * 4;
        float4 t = *(const float4*)(bc + (size_t)(s0 + r)*128 + c4);
        float vv[4] = {t.x, t.y, t.z, t.w};
#pragma unroll
        for (int k = 0; k < 4; k++) {
            __nv_bfloat16 h, l;
            split2(vv[k], h, l);
            if (c4 < 64) { sBh[r*SQ + c4 + k] = h; sBl[r*SQ + c4 + k] = l; }
            else         { sMh[r*SQ + c4 - 64 + k] = h; sMl[r*SQ + c4 - 64 + k] = l; }
        }
    }
    // ---- fused conv+SiLU for x only (head-private channels) -----------------
    {
        int cg4 = (tid & 15) * 4;
        int rb = (tid >> 4) * 4;
        int ch = hh*HD + cg4;   // conv channel
        float v[7][4];
#pragma unroll
        for (int k = 0; k < 7; k++) {
            int ls = s0 + rb - 3 + k;
            if (ls >= 0) {
                float4 t = *(const float4*)(zx + (size_t)ls*DIP + DI + ch);
                v[k][0]=t.x; v[k][1]=t.y; v[k][2]=t.z; v[k][3]=t.w;
            } else { v[k][0]=0.f; v[k][1]=0.f; v[k][2]=0.f; v[k][3]=0.f; }
        }
        float4 wch[4]; float bch[4];
#pragma unroll
        for (int c = 0; c < 4; c++) {
            wch[c] = *(const float4*)(cw + ((size_t)li*CD + ch + c)*4);
            bch[c] = cbias[(size_t)li*CD + ch + c];
        }
#pragma unroll
        for (int j = 0; j < 4; j++) {
            int r = rb + j;
#pragma unroll
            for (int c = 0; c < 4; c++) {
                float a = v[j][c]*wch[c].x + v[j+1][c]*wch[c].y
                        + v[j+2][c]*wch[c].z + v[j+3][c]*wch[c].w + bch[c];
                float s = a / (1.f + __expf(-a));
                __nv_bfloat16 h, l;
                split2(s, h, l);
                sXh[(cg4 + c)*SQ + r] = h; sXl[(cg4 + c)*SQ + r] = l;
            }
        }
    }
    if (tid < QCH) sdtr[tid] = dtp[(size_t)(s0 + tid)*NH + hh];
    __syncthreads();

    int wm = warp & 1, wn = warp >> 1;
    uint32_t baseBh = smem_u32(sBh), baseBl = smem_u32(sBl);
    uint32_t baseMh = smem_u32(sMh), baseMl = smem_u32(sMl);
    uint32_t baseXh = smem_u32(sXh), baseXl = smem_u32(sXl);
    uint32_t baseTh = baseBh, baseTl = baseBl;
    int a_r = lane & 15, a_k = (lane >> 4) << 3;
    int b_r = ((lane >> 4) & 1)*8 + (lane & 7);
    int b_k = ((lane >> 3) & 1)*8;

    float accG[2][2][4];
#pragma unroll
    for (int mi = 0; mi < 2; mi++)
#pragma unroll
        for (int ni = 0; ni < 2; ni++)
#pragma unroll
            for (int e = 0; e < 4; e++) accG[mi][ni][e] = 0.f;

#pragma unroll
    for (int kk = 0; kk < 4; kk++) {
        uint32_t ah[2][4], al[2][4];
#pragma unroll
        for (int mi = 0; mi < 2; mi++) {
            int off = ((wm*32 + mi*16 + a_r)*SQ + kk*16 + a_k) * 2;
            ldsm_x4(ah[mi], baseMh + off);
            ldsm_x4(al[mi], baseMl + off);
        }
        int boff = ((wn*16 + b_r)*SQ + kk*16 + b_k) * 2;
        uint32_t th[4], tl[4];
        ldsm_x4(th, baseBh + boff);
        ldsm_x4(tl, baseBl + boff);
        uint32_t bh[2][2] = {{th[0], th[1]}, {th[2], th[3]}};
        uint32_t bl[2][2] = {{tl[0], tl[1]}, {tl[2], tl[3]}};
#pragma unroll
        for (int mi = 0; mi < 2; mi++)
#pragma unroll
            for (int ni = 0; ni < 2; ni++) {
                mma16816(accG[mi][ni], ah[mi], bh[ni]);
                mma16816(accG[mi][ni], ah[mi], bl[ni]);
                mma16816(accG[mi][ni], al[mi], bh[ni]);
            }
    }
    __syncthreads();

    if (tid < QCH) {
        float s = sdtr[tid];
#pragma unroll
        for (int o = 1; o < 32; o <<= 1) {
            float t = __shfl_up_sync(0xffffffffu, s, o);
            if ((tid & 31) >= o) s += t;
        }
        sdt[tid] = s;
    }
    __syncthreads();
    if (tid >= 32 && tid < QCH) sdt[tid] += sdt[31];
    __syncthreads();
    float S = sdt[QCH-1];
    if (tid < QCH) sdt_g[s0 + tid] = sdt[tid];
    if (tid == 0) g_scratch[OFF_CSUM + hg*NCHUNK + chunk] = S;

    // ---- build Bw^T into the SAME region as B: read to regs, bar, write ----
    {
        int bi = tid >> 2, nb = (tid & 3) * 16;
        float wv = __expf(Aa * (S - sdt[bi])) * sdtr[bi];
        float fv[16];
#pragma unroll
        for (int n = 0; n < 16; n++) {
            int nn = nb + n;
            fv[n] = wv * (__bfloat162float(sBh[bi*SQ + nn]) + __bfloat162float(sBl[bi*SQ + nn]));
        }
        __syncthreads();
#pragma unroll
        for (int n = 0; n < 16; n++) {
            int nn = nb + n;
            __nv_bfloat16 h, l;
            split2(fv[n], h, l);
            sTh[nn*SQ + bi] = h; sTl[nn*SQ + bi] = l;
        }
    }

#pragma unroll
    for (int mi = 0; mi < 2; mi++)
#pragma unroll
        for (int ni = 0; ni < 2; ni++)
#pragma unroll
            for (int pe = 0; pe < 2; pe++) {
                int j  = wm*32 + mi*16 + (lane >> 2) + pe*8;
                int i0 = wn*16 + ni*8 + (lane & 3)*2;
                float m0v = 0.f, m1v = 0.f;
                if (j >= i0) {
                    m0v = accG[mi][ni][pe*2+0] * __expf(Aa*(sdt[j]-sdt[i0])) * sdtr[i0];
                    if (j == i0) m0v += Dv;
                }
                int i1 = i0 + 1;
                if (j >= i1) {
                    m1v = accG[mi][ni][pe*2+1] * __expf(Aa*(sdt[j]-sdt[i1])) * sdtr[i1];
                    if (j == i1) m1v += Dv;
                }
                __nv_bfloat16 h0, l0, h1, l1;
                split2(m0v, h0, l0); split2(m1v, h1, l1);
                __nv_bfloat162 hh2; hh2.x = h0; hh2.y = h1;
                __nv_bfloat162 ll2; ll2.x = l0; ll2.y = l1;
                *(__nv_bfloat162*)&sMh[j*SQ + i0] = hh2;
                *(__nv_bfloat162*)&sMl[j*SQ + i0] = ll2;
            }
    __syncthreads();

    float accY[2][2][4], accH[2][2][4];
#pragma unroll
    for (int mi = 0; mi < 2; mi++)
#pragma unroll
        for (int ni = 0; ni < 2; ni++)
#pragma unroll
            for (int e = 0; e < 4; e++) { accY[mi][ni][e] = 0.f; accH[mi][ni][e] = 0.f; }

#pragma unroll
    for (int kk = 0; kk < 4; kk++) {
        int boff = ((wn*16 + b_r)*SQ + kk*16 + b_k) * 2;
        uint32_t th[4], tl[4];
        ldsm_x4(th, baseXh + boff);
        ldsm_x4(tl, baseXl + boff);
        uint32_t xh[2][2] = {{th[0], th[1]}, {th[2], th[3]}};
        uint32_t xl[2][2] = {{tl[0], tl[1]}, {tl[2], tl[3]}};
        uint32_t mh[2][4], ml[2][4], hhh[2][4], hll[2][4];
#pragma unroll
        for (int mi = 0; mi < 2; mi++) {
            int off = ((wm*32 + mi*16 + a_r)*SQ + kk*16 + a_k) * 2;
            ldsm_x4(mh[mi], baseMh + off);
            ldsm_x4(ml[mi], baseMl + off);
            ldsm_x4(hhh[mi], baseTh + off);
            ldsm_x4(hll[mi], baseTl + off);
        }
#pragma unroll
        for (int mi = 0; mi < 2; mi++)
#pragma unroll
            for (int ni = 0; ni < 2; ni++) {
                mma16816(accY[mi][ni], mh[mi], xh[ni]);
                mma16816(accY[mi][ni], mh[mi], xl[ni]);
                mma16816(accY[mi][ni], ml[mi], xh[ni]);
                mma16816(accH[mi][ni], hhh[mi], xh[ni]);
                mma16816(accH[mi][ni], hhh[mi], xl[ni]);
                mma16816(accH[mi][ni], hll[mi], xh[ni]);
            }
    }

#pragma unroll
    for (int mi = 0; mi < 2; mi++)
#pragma unroll
        for (int ni = 0; ni < 2; ni++)
#pragma unroll
            for (int pe = 0; pe < 2; pe++) {
                int j = wm*32 + mi*16 + (lane >> 2) + pe*8;
                int p = wn*16 + ni*8 + (lane & 3)*2;
                *(float2*)(y + (size_t)(s0 + j)*DI + hh*HD + p) =
                    make_float2(accY[mi][ni][pe*2+0], accY[mi][ni][pe*2+1]);
            }

    __syncthreads();
#pragma unroll
    for (int mi = 0; mi < 2; mi++)
#pragma unroll
        for (int ni = 0; ni < 2; ni++)
#pragma unroll
            for (int pe = 0; pe < 2; pe++) {
                int n = wm*32 + mi*16 + (lane >> 2) + pe*8;
                int p = wn*16 + ni*8 + (lane & 3)*2;
                *(float2*)&sStage[n*66 + p] =
                    make_float2(accH[mi][ni][pe*2+0], accH[mi][ni][pe*2+1]);
            }
    __syncthreads();
    {
        float* hl = g_scratch + OFF_HLOC + ((size_t)hg*NCHUNK + chunk)*(HD*DS);
        int p = tid >> 2, nb = (tid & 3) * 16;
#pragma unroll
        for (int v2 = 0; v2 < 4; v2++) {
            int n = nb + v2*4;
            float4 o = make_float4(sStage[(n+0)*66 + p], sStage[(n+1)*66 + p],
                                   sStage[(n+2)*66 + p], sStage[(n+3)*66 + p]);
            *(float4*)(hl + (size_t)p*DS + n) = o;
        }
    }
}

// ---------------- scan pass 2: inter-chunk state carry -----------------------
__global__ __launch_bounds__(256) void k_scan2(const float* __restrict__ A_log, int layer) {
    int hg = blockIdx.x >> 4;
    int e  = (blockIdx.x & 15)*256 + threadIdx.x;
    int dir = hg >> 4, hh = hg & 7;
    int li = dir*NLAYERS + layer;
    float Aa = -expf(A_log[li*NH + hh]);
    const float* csum = g_scratch + OFF_CSUM + hg*NCHUNK;
    float* hl = g_scratch + OFF_HLOC + (size_t)hg*NCHUNK*(HD*DS) + e;
    float tmp[NCHUNK];
#pragma unroll
    for (int c = 0; c < NCHUNK; c++) tmp[c] = hl[(size_t)c*(HD*DS)];
    float carry = 0.f;
#pragma unroll
    for (int c = 0; c < NCHUNK; c++) {
        hl[(size_t)c*(HD*DS)] = carry;
        carry = carry * __expf(Aa * csum[c]) + tmp[c];
    }
}

// ---------------- scan pass 3: HMMA correction  y += cum∘(C·H_in) ------------
__global__ __launch_bounds__(256) void k_scan3(const float* __restrict__ A_log, int layer) {
    __shared__ __align__(16) __nv_bfloat16 sCh[64*SQ];
    __shared__ __align__(16) __nv_bfloat16 sCl[64*SQ];
    __shared__ __align__(16) __nv_bfloat16 sHh[64*SQ];
    __shared__ __align__(16) __nv_bfloat16 sHl[64*SQ];
    __shared__ float scum[QCH];

    int idx = blockIdx.x;
    int chunk = idx & 15; idx >>= 4;
    if (chunk == 0) return;
    int hh = idx & 7; idx >>= 3;
    int b = idx & 1; int dir = idx >> 1;
    int hg = (dir*2 + b)*8 + hh;
    int tid = threadIdx.x;
    int warp = tid >> 5, lane = tid & 31;
    int li = dir*NLAYERS + layer;
    float Aa = -expf(A_log[li*NH + hh]);
    const float* ccb = g_scratch + OFF_BC + ((size_t)dir*M2 + (size_t)b*LSEQ)*128 + 64;
    float* y         = g_scratch + OFF_Y  + (size_t)dir*M2*DI + (size_t)b*LSEQ*DI;
    const float* sdt_g = g_scratch + OFF_SDT + (size_t)hg*LSEQ;
    const float* hloc  = g_scratch + OFF_HLOC + ((size_t)hg*NCHUNK + chunk)*(HD*DS);
    int s0 = chunk * QCH;

#pragma unroll
    for (int i = 0; i < 4; i++) {
        int id = tid + i*256;
        int r = id >> 4, c4 = (id & 15) * 4;
        float4 cv = *(const float4*)(ccb + (size_t)(s0 + r)*128 + c4);
        float4 hv = *(const float4*)(hloc + (size_t)r*DS + c4);
        float ccv[4] = {cv.x, cv.y, cv.z, cv.w};
        float hhv[4] = {hv.x, hv.y, hv.z, hv.w};
#pragma unroll
        for (int k = 0; k < 4; k++) {
            __nv_bfloat16 h, l;
            split2(ccv[k], h, l);
            sCh[r*SQ + c4 + k] = h; sCl[r*SQ + c4 + k] = l;
            split2(hhv[k], h, l);
            sHh[r*SQ + c4 + k] = h; sHl[r*SQ + c4 + k] = l;
        }
    }
    if (tid < QCH) scum[tid] = __expf(Aa * sdt_g[s0 + tid]);
    __syncthreads();

    int wm = warp & 1, wn = warp >> 1;
    uint32_t baseCh = smem_u32(sCh), baseCl = smem_u32(sCl);
    uint32_t baseHh = smem_u32(sHh), baseHl = smem_u32(sHl);
    int a_r = lane & 15, a_k = (lane >> 4) << 3;
    int b_r = ((lane >> 4) & 1)*8 + (lane & 7);
    int b_k = ((lane >> 3) & 1)*8;

    float accY[2][2][4];
#pragma unroll
    for (int mi = 0; mi < 2; mi++)
#pragma unroll
        for (int ni = 0; ni < 2; ni++)
#pragma unroll
            for (int e = 0; e < 4; e++) accY[mi][ni][e] = 0.f;

#pragma unroll
    for (int kk = 0; kk < 4; kk++) {
        uint32_t ah[2][4], al[2][4];
#pragma unroll
        for (int mi = 0; mi < 2; mi++) {
            int off = ((wm*32 + mi*16 + a_r)*SQ + kk*16 + a_k) * 2;
            ldsm_x4(ah[mi], baseCh + off);
            ldsm_x4(al[mi], baseCl + off);
        }
        int boff = ((wn*16 + b_r)*SQ + kk*16 + b_k) * 2;
        uint32_t th[4], tl[4];
        ldsm_x4(th, baseHh + boff);
        ldsm_x4(tl, baseHl + boff);
        uint32_t bh[2][2] = {{th[0], th[1]}, {th[2], th[3]}};
        uint32_t bl[2][2] = {{tl[0], tl[1]}, {tl[2], tl[3]}};
#pragma unroll
        for (int mi = 0; mi < 2; mi++)
#pragma unroll
            for (int ni = 0; ni < 2; ni++) {
                mma16816(accY[mi][ni], ah[mi], bh[ni]);
                mma16816(accY[mi][ni], ah[mi], bl[ni]);
                mma16816(accY[mi][ni], al[mi], bh[ni]);
            }
    }

#pragma unroll
    for (int mi = 0; mi < 2; mi++)
#pragma unroll
        for (int ni = 0; ni < 2; ni++)
#pragma unroll
            for (int pe = 0; pe < 2; pe++) {
                int j = wm*32 + mi*16 + (lane >> 2) + pe*8;
                int p = wn*16 + ni*8 + (lane & 3)*2;
                float cum = scum[j];
                float* yp = y + (size_t)(s0 + j)*DI + hh*HD + p;
                float2 old = *(float2*)yp;
                old.x += cum * accY[mi][ni][pe*2+0];
                old.y += cum * accY[mi][ni][pe*2+1];
                *(float2*)yp = old;
            }
}

// ---------------- gated RMSNorm (writes bf16 hi/lo for out_proj) -------------
__global__ __launch_bounds__(512) void k_gatedrms(const float* __restrict__ nw, int layer) {
    int dir = blockIdx.y;
    int m = blockIdx.x;
    int i = threadIdx.x;
    int li = dir*NLAYERS + layer;
    float yv = g_scratch[OFF_Y + (size_t)dir*M2*DI + (size_t)m*DI + i];
    float zv = g_scratch[OFF_ZX + (size_t)dir*M2*DIP + (size_t)m*DIP + i];
    float g = yv * (zv / (1.f + __expf(-zv)));
    float ss = g * g;
#pragma unroll
    for (int o = 16; o > 0; o >>= 1) ss += __shfl_xor_sync(0xffffffffu, ss, o);
    __shared__ float red[16];
    if ((i & 31) == 0) red[i >> 5] = ss;
    __syncthreads();
    if (i < 32) {
        float v = (i < 16) ? red[i] : 0.f;
#pragma unroll
        for (int o = 8; o > 0; o >>= 1) v += __shfl_xor_sync(0xffffffffu, v, o);
        if (i == 0) red[0] = v;
    }
    __syncthreads();
    float inv = rsqrtf(red[0] * (1.f/DI) + 1e-5f);
    float o = g * inv * nw[(size_t)li*DI + i];
    size_t oi = (size_t)dir*M2*DI + (size_t)m*DI + i;
    __nv_bfloat16 hb, lb;
    split2(o, hb, lb);
    g_bf[B_NRMH + oi] = hb;
    g_bf[B_NRML + oi] = lb;
}

// ---------------- combine fwd + flipped bwd (bf16 hi/lo) ---------------------
__global__ void k_comb() {
    int m = blockIdx.x;
    int i = threadIdx.x;
    int b = m / LSEQ, l = m % LSEQ;
    float v;
    if (i < DM) v = g_scratch[OFF_H + (size_t)m*DM + i];
    else        v = g_scratch[OFF_H + (size_t)M2*DM + ((size_t)b*LSEQ + (LSEQ-1-l))*DM + (i-DM)];
    size_t oi = (size_t)m*2*DM + i;
    __nv_bfloat16 hb, lb;
    split2(v, hb, lb);
    g_bf[B_COMBH + oi] = hb;
    g_bf[B_COMBL + oi] = lb;
}

// ---------------- gate sigmoid + fuse + LayerNorm ---------------------------
__global__ __launch_bounds__(256) void k_final(const float* __restrict__ fb,
                                               const float* __restrict__ lnw,
                                               const float* __restrict__ lnb,
                                               float* __restrict__ out) {
    int m = blockIdx.x;
    int d = threadIdx.x;
    int b = m / LSEQ, l = m % LSEQ;
    float gl0 = g_scratch[OFF_GATE + (size_t)m*2*DM + d] + fb[d];
    float gl1 = g_scratch[OFF_GATE + (size_t)m*2*DM + DM + d] + fb[DM + d];
    float gf = 1.f / (1.f + __expf(-gl0));
    float gb = 1.f / (1.f + __expf(-gl1));
    float fwd = g_scratch[OFF_H + (size_t)m*DM + d];
    float bwd = g_scratch[OFF_H + (size_t)M2*DM + ((size_t)b*LSEQ + (LSEQ-1-l))*DM + d];
    float fu = gf*fwd + gb*bwd;

    float s1 = fu, s2 = fu*fu;
#pragma unroll
    for (int o = 16; o > 0; o >>= 1) {
        s1 += __shfl_xor_sync(0xffffffffu, s1, o);
        s2 += __shfl_xor_sync(0xffffffffu, s2, o);
    }
    __shared__ float r1[8], r2[8];
    if ((d & 31) == 0) { r1[d >> 5] = s1; r2[d >> 5] = s2; }
    __syncthreads();
    if (d < 32) {
        float v1 = (d < 8) ? r1[d] : 0.f;
        float v2 = (d < 8) ? r2[d] : 0.f;
#pragma unroll
        for (int o = 4; o > 0; o >>= 1) {
            v1 += __shfl_xor_sync(0xffffffffu, v1, o);
            v2 += __shfl_xor_sync(0xffffffffu, v2, o);
        }
        if (d == 0) { r1[0] = v1; r2[0] = v2; }
    }
    __syncthreads();
    float mu = r1[0] * (1.f/DM);
    float var = r2[0] * (1.f/DM) - mu*mu;
    float inv = rsqrtf(var + 1e-5f);
    out[(size_t)m*DM + d] = (fu - mu) * inv * lnw[d] + lnb[d];
}

// ---------------------------------------------------------------------------
extern "C" void kernel_launch(void* const* d_in, const int* in_sizes, int n_in,
                              void* d_out, int out_size) {
    const int*   ids  = (const int*)d_in[0];
    const float* mask = (const float*)d_in[1];
    const float* tok  = (const float*)d_in[2];
    const float* pos  = (const float*)d_in[3];
    const float* inw  = (const float*)d_in[4];
    const float* cw   = (const float*)d_in[5];
    const float* cb   = (const float*)d_in[6];
    const float* dtb  = (const float*)d_in[7];
    const float* alog = (const float*)d_in[8];
    const float* dpar = (const float*)d_in[9];
    const float* nw   = (const float*)d_in[10];
    const float* ow   = (const float*)d_in[11];
    const float* fw   = (const float*)d_in[12];
    const float* fb   = (const float*)d_in[13];
    const float* lnw  = (const float*)d_in[14];
    const float* lnb  = (const float*)d_in[15];

    cudaFuncSetAttribute(k_scan1, cudaFuncAttributeMaxDynamicSharedMemorySize, SCAN_SMEM);
    cudaFuncSetAttribute(k_mma_gemm, cudaFuncAttributeMaxDynamicSharedMemorySize, GEMM_SMEM);
    cudaFuncSetAttribute(k_mma_gemm64, cudaFuncAttributeMaxDynamicSharedMemorySize, G64_SMEM);

    float* scr = nullptr;
    cudaGetSymbolAddress((void**)&scr, g_scratch);
    float* pH    = scr + OFF_H;
    float* pZX   = scr + OFF_ZX;
    float* pGATE = scr + OFF_GATE;

    {
        int n1 = 2*NLAYERS*DIP*DM;
        int n2 = 2*NLAYERS*DM*DI;
        int n3 = (2*DM)*(2*DM);
        int tot = n1 + n2 + n3;
        k_cvt3<<<(tot/4 + 255)/256, 256>>>(inw, n1, ow, n2, fw, n3);
    }

    k_embed<<<M2, DM>>>(ids, mask, tok, pos);

    for (int layer = 0; layer < NLAYERS; layer++) {
        k_mma_gemm<<<dim3((DIP + 63)/64, M2/128, 2), 256, GEMM_SMEM>>>(
            B_ACTH, B_ACTL,
            B_WINH + (size_t)layer*DIP*DM, B_WINL + (size_t)layer*DIP*DM,
            pZX, M2, DIP, DM,
            (long)M2*DM, (long)NLAYERS*DIP*DM, (long)M2*DIP,
            0, 0, 0);
        k_convbc<<<dim3(M2, 2), 128>>>(cw, cb, dtb, layer);
        k_scan1<<<512, 256, SCAN_SMEM>>>(alog, dpar, cw, cb, layer);
        k_scan2<<<512, 256>>>(alog, layer);
        k_scan3<<<512, 256>>>(alog, layer);
        k_gatedrms<<<dim3(M2, 2), DI>>>(nw, layer);
        int wrBf = (layer + 1 < NLAYERS) ? 1 : 0;
        k_mma_gemm64<<<dim3(DM/64, M2/64, 2), 256, G64_SMEM>>>(
            B_NRMH, B_NRML,
            B_WOUTH + (size_t)layer*DM*DI, B_WOUTL + (size_t)layer*DM*DI,
            pH, M2, DM, DI,
            (long)M2*DI, (long)NLAYERS*DM*DI, (long)M2*DM,
            B_ACTH, B_ACTL, wrBf);
    }

    k_comb<<<M2, 2*DM>>>();
    k_mma_gemm64<<<dim3(2*DM/64, M2/64, 1), 256, G64_SMEM>>>(
        B_COMBH, B_COMBL, B_WFUSH, B_WFUSL,
        pGATE, M2, 2*DM, 2*DM, 0, 0, 0,
        0, 0, 0);
    k_final<<<M2, DM>>>(fb, lnw, lnb, (float*)d_out);
}

// round 17
// speedup vs baseline: 1.0492x; 1.0332x over previous
#include <cuda_runtime.h>
#include <cuda_bf16.h>
#include <math.h>
#include <cstdint>

#define BB 2
#define LSEQ 1024
#define DM 256
#define DI 512
#define DS 64
#define NH 8
#define HD 64
#define CD 640
#define DIP 1160
#define M2 (BB*LSEQ)
#define NLAYERS 2
#define NCHUNK 16
#define QCH 64

// ------------------------- fp32 scratch -------------------------------------
static constexpr size_t OFF_H    = 0;
static constexpr size_t OFF_ZX   = OFF_H    + (size_t)2*M2*DM;
static constexpr size_t OFF_BC   = OFF_ZX   + (size_t)2*M2*DIP;   // conv(B,C): [dir][bl][128]
static constexpr size_t OFF_DTB  = OFF_BC   + (size_t)2*M2*128;   // softplus dt
static constexpr size_t OFF_Y    = OFF_DTB  + (size_t)2*M2*NH;
static constexpr size_t OFF_GATE = OFF_Y    + (size_t)2*M2*DI;
static constexpr size_t OFF_HLOC = OFF_GATE + (size_t)M2*2*DM;
static constexpr size_t OFF_SDT  = OFF_HLOC + (size_t)32*NCHUNK*HD*DS;
static constexpr size_t OFF_CSUM = OFF_SDT  + (size_t)32*LSEQ;
static constexpr size_t SCRATCH_TOTAL = OFF_CSUM + (size_t)32*NCHUNK;

__device__ float g_scratch[SCRATCH_TOTAL];

// ------------------------- bf16 hi/lo scratch -------------------------------
static constexpr size_t B_ACTH  = 0;
static constexpr size_t B_ACTL  = B_ACTH  + (size_t)2*M2*DM;
static constexpr size_t B_NRMH  = B_ACTL  + (size_t)2*M2*DM;
static constexpr size_t B_NRML  = B_NRMH  + (size_t)2*M2*DI;
static constexpr size_t B_COMBH = B_NRML  + (size_t)2*M2*DI;
static constexpr size_t B_COMBL = B_COMBH + (size_t)M2*2*DM;
static constexpr size_t B_WINH  = B_COMBL + (size_t)M2*2*DM;
static constexpr size_t B_WINL  = B_WINH  + (size_t)2*NLAYERS*DIP*DM;
static constexpr size_t B_WOUTH = B_WINL  + (size_t)2*NLAYERS*DIP*DM;
static constexpr size_t B_WOUTL = B_WOUTH + (size_t)2*NLAYERS*DM*DI;
static constexpr size_t B_WFUSH = B_WOUTL + (size_t)2*NLAYERS*DM*DI;
static constexpr size_t B_WFUSL = B_WFUSH + (size_t)(2*DM)*(2*DM);
static constexpr size_t BF_TOTAL = B_WFUSL + (size_t)(2*DM)*(2*DM);

__device__ __align__(16) __nv_bfloat16 g_bf[BF_TOTAL];

typedef unsigned long long ull;

// ---- HMMA helpers -----------------------------------------------------------
__device__ __forceinline__ uint32_t smem_u32(const void* p) {
    uint32_t a;
    asm("{ .reg .u64 t; cvta.to.shared.u64 t, %1; cvt.u32.u64 %0, t; }" : "=r"(a) : "l"(p));
    return a;
}
__device__ __forceinline__ void ldsm_x4(uint32_t* r, uint32_t addr) {
    asm volatile("ldmatrix.sync.aligned.m8n8.x4.shared.b16 {%0,%1,%2,%3}, [%4];"
        : "=r"(r[0]), "=r"(r[1]), "=r"(r[2]), "=r"(r[3]) : "r"(addr));
}
__device__ __forceinline__ void mma16816(float* d, const uint32_t* a, const uint32_t* b) {
    asm volatile("mma.sync.aligned.m16n8k16.row.col.f32.bf16.bf16.f32 "
        "{%0,%1,%2,%3}, {%4,%5,%6,%7}, {%8,%9}, {%0,%1,%2,%3};"
        : "+f"(d[0]), "+f"(d[1]), "+f"(d[2]), "+f"(d[3])
        : "r"(a[0]), "r"(a[1]), "r"(a[2]), "r"(a[3]), "r"(b[0]), "r"(b[1]));
}
__device__ __forceinline__ void split2(float v, __nv_bfloat16& h, __nv_bfloat16& l) {
    h = __float2bfloat16(v);
    l = __float2bfloat16(v - __bfloat162float(h));
}
__device__ __forceinline__ void cp16(uint32_t d, const void* s) {
    asm volatile("cp.async.ca.shared.global [%0], [%1], 16;" :: "r"(d), "l"(s));
}
__device__ __forceinline__ void cp16z(uint32_t d, const void* s, int sz) {
    asm volatile("cp.async.ca.shared.global [%0], [%1], 16, %2;" :: "r"(d), "l"(s), "r"(sz));
}
#define CP_COMMIT() asm volatile("cp.async.commit_group;" ::: "memory")
#define CP_WAIT0()  asm volatile("cp.async.wait_group 0;" ::: "memory")

// ---------------- fused fp32 -> bf16 hi/lo conversion (3 weight arrays) ------
__global__ void k_cvt3(const float* __restrict__ w1, int n1,
                       const float* __restrict__ w2, int n2,
                       const float* __restrict__ w3, int n3) {
    int i = (blockIdx.x*blockDim.x + threadIdx.x)*4;
    const float* x; size_t oh, ol; int base;
    if (i < n1)            { x = w1; oh = B_WINH;  ol = B_WINL;  base = 0; }
    else if (i < n1 + n2)  { x = w2; oh = B_WOUTH; ol = B_WOUTL; base = n1; }
    else if (i < n1+n2+n3) { x = w3; oh = B_WFUSH; ol = B_WFUSL; base = n1 + n2; }
    else return;
    int ii = i - base;
    float4 v = *(const float4*)(x + ii);
    float vv[4] = {v.x, v.y, v.z, v.w};
#pragma unroll
    for (int k = 0; k < 4; k++) {
        __nv_bfloat16 h, l;
        split2(vv[k], h, l);
        g_bf[oh + ii + k] = h;
        g_bf[ol + ii + k] = l;
    }
}

// ---------------- HMMA split-bf16 GEMM 128x64, cp.async double-buffered ------
#define KC 32
#define SA 40
#define GA_BUF 10240
#define GW_BUF 5120
#define GEMM_SMEM (2*GA_BUF*2 + 2*GW_BUF*2)

__global__ __launch_bounds__(256) void k_mma_gemm(
        size_t oAh, size_t oAl, size_t oWh, size_t oWl,
        float* __restrict__ C, int M, int N, int K,
        long sAz, long sWz, long sCz,
        size_t oCh, size_t oCl, int wrBf) {
    const __nv_bfloat16* Ah = g_bf + oAh + (long)blockIdx.z * sAz;
    const __nv_bfloat16* Al = g_bf + oAl + (long)blockIdx.z * sAz;
    const __nv_bfloat16* Wh = g_bf + oWh + (long)blockIdx.z * sWz;
    const __nv_bfloat16* Wl = g_bf + oWl + (long)blockIdx.z * sWz;
    C += (long)blockIdx.z * sCz;
    size_t oChz = oCh + (long)blockIdx.z * sCz;
    size_t oClz = oCl + (long)blockIdx.z * sCz;

    extern __shared__ char gsm[];
    uint32_t aAh = smem_u32(gsm);
    uint32_t aAl = aAh + 2*GA_BUF;
    uint32_t aWh = aAl + 2*GA_BUF;
    uint32_t aWl = aWh + 2*GW_BUF;

    int tid = threadIdx.x;
    int warp = tid >> 5, lane = tid & 31;
    int wm = warp & 3, wn = warp >> 2;
    int m0 = blockIdx.y * 128, n0 = blockIdx.x * 64;

    float acc[2][4][4];
#pragma unroll
    for (int i = 0; i < 2; i++)
#pragma unroll
        for (int j = 0; j < 4; j++)
#pragma unroll
            for (int k = 0; k < 4; k++) acc[i][j][k] = 0.f;

    int a_r  = (lane & 15);
    int a_k  = (lane >> 4) << 3;

    int srA = tid >> 2, scA = (tid & 3) * 8;
    int srW = tid >> 2, scW = (tid & 3) * 8;
    int wrow = n0 + srW;
    int wsz = (wrow < N) ? 16 : 0;
    int wclamp = (wrow < N) ? wrow : (N - 1);

    int KT = K / KC;

    {
        int k0 = 0;
#pragma unroll
        for (int i = 0; i < 2; i++) {
            int r = srA + i*64;
            uint32_t d = (uint32_t)((r*SA + scA) * 2);
            cp16(aAh + d, Ah + (size_t)(m0 + r)*K + k0 + scA);
            cp16(aAl + d, Al + (size_t)(m0 + r)*K + k0 + scA);
        }
        uint32_t d = (uint32_t)((srW*SA + scW) * 2);
        cp16z(aWh + d, Wh + (size_t)wclamp*K + k0 + scW, wsz);
        cp16z(aWl + d, Wl + (size_t)wclamp*K + k0 + scW, wsz);
        CP_COMMIT();
    }

    int buf = 0;
    for (int c = 0; c < KT; c++) {
        CP_WAIT0();
        __syncthreads();
        if (c + 1 < KT) {
            int k0 = (c + 1) * KC;
            uint32_t oA = (uint32_t)((buf ^ 1) * GA_BUF);
            uint32_t oW = (uint32_t)((buf ^ 1) * GW_BUF);
#pragma unroll
            for (int i = 0; i < 2; i++) {
                int r = srA + i*64;
                uint32_t d = oA + (uint32_t)((r*SA + scA) * 2);
                cp16(aAh + d, Ah + (size_t)(m0 + r)*K + k0 + scA);
                cp16(aAl + d, Al + (size_t)(m0 + r)*K + k0 + scA);
            }
            uint32_t d = oW + (uint32_t)((srW*SA + scW) * 2);
            cp16z(aWh + d, Wh + (size_t)wclamp*K + k0 + scW, wsz);
            cp16z(aWl + d, Wl + (size_t)wclamp*K + k0 + scW, wsz);
            CP_COMMIT();
        }

        uint32_t bAh = aAh + buf*GA_BUF, bAl = aAl + buf*GA_BUF;
        uint32_t bWh = aWh + buf*GW_BUF, bWl = aWl + buf*GW_BUF;
#pragma unroll
        for (int km = 0; km < 2; km++) {
            uint32_t ah[2][4], al[2][4], bh[4][2], bl[4][2];
#pragma unroll
            for (int mi = 0; mi < 2; mi++) {
                int off = ((wm*32 + mi*16 + a_r)*SA + km*16 + a_k) * 2;
                ldsm_x4(ah[mi], bAh + off);
                ldsm_x4(al[mi], bAl + off);
            }
#pragma unroll
            for (int np = 0; np < 2; np++) {
                int row = wn*32 + (np*2 + ((lane >> 4) & 1))*8 + (lane & 7);
                int off = (row*SA + km*16 + ((lane >> 3) & 1) * 8) * 2;
                uint32_t t4[4];
                ldsm_x4(t4, bWh + off);
                bh[np*2][0] = t4[0]; bh[np*2][1] = t4[1];
                bh[np*2+1][0] = t4[2]; bh[np*2+1][1] = t4[3];
                ldsm_x4(t4, bWl + off);
                bl[np*2][0] = t4[0]; bl[np*2][1] = t4[1];
                bl[np*2+1][0] = t4[2]; bl[np*2+1][1] = t4[3];
            }
#pragma unroll
            for (int mi = 0; mi < 2; mi++)
#pragma unroll
                for (int ni = 0; ni < 4; ni++) {
                    mma16816(acc[mi][ni], ah[mi], bh[ni]);
                    mma16816(acc[mi][ni], ah[mi], bl[ni]);
                    mma16816(acc[mi][ni], al[mi], bh[ni]);
                }
        }
        __syncthreads();
        buf ^= 1;
    }

#pragma unroll
    for (int mi = 0; mi < 2; mi++) {
#pragma unroll
        for (int ni = 0; ni < 4; ni++) {
            int m = m0 + wm*32 + mi*16 + (lane >> 2);
            int n = n0 + wn*32 + ni*8 + (lane & 3)*2;
            if (n < N) {
#pragma unroll
                for (int hrow = 0; hrow < 2; hrow++) {
                    int mm = m + hrow*8;
                    float v0 = acc[mi][ni][hrow*2 + 0];
                    float v1 = acc[mi][ni][hrow*2 + 1];
                    *(float2*)(C + (size_t)mm*N + n) = make_float2(v0, v1);
                    if (wrBf) {
                        __nv_bfloat16 h0, l0, h1, l1;
                        split2(v0, h0, l0); split2(v1, h1, l1);
                        __nv_bfloat162 hh; hh.x = h0; hh.y = h1;
                        __nv_bfloat162 ll; ll.x = l0; ll.y = l1;
                        *(__nv_bfloat162*)(g_bf + oChz + (size_t)mm*N + n) = hh;
                        *(__nv_bfloat162*)(g_bf + oClz + (size_t)mm*N + n) = ll;
                    }
                }
            }
        }
    }
}

// ---------------- HMMA split-bf16 GEMM 64x64 (for small-N GEMMs) -------------
// wrBf: 0 = fp32 only; 1 = +bf16 acts at oCh/oCl; 2 = +bf16 COMB (dir-flipped)
#define G64_BUF 5120
#define G64_SMEM (8*G64_BUF)

__global__ __launch_bounds__(256) void k_mma_gemm64(
        size_t oAh, size_t oAl, size_t oWh, size_t oWl,
        float* __restrict__ C, int M, int N, int K,
        long sAz, long sWz, long sCz,
        size_t oCh, size_t oCl, int wrBf) {
    const __nv_bfloat16* Ah = g_bf + oAh + (long)blockIdx.z * sAz;
    const __nv_bfloat16* Al = g_bf + oAl + (long)blockIdx.z * sAz;
    const __nv_bfloat16* Wh = g_bf + oWh + (long)blockIdx.z * sWz;
    const __nv_bfloat16* Wl = g_bf + oWl + (long)blockIdx.z * sWz;
    C += (long)blockIdx.z * sCz;
    size_t oChz = oCh + (long)blockIdx.z * sCz;
    size_t oClz = oCl + (long)blockIdx.z * sCz;

    extern __shared__ char gsm[];
    uint32_t aAh = smem_u32(gsm);
    uint32_t aAl = aAh + 2*G64_BUF;
    uint32_t aWh = aAl + 2*G64_BUF;
    uint32_t aWl = aWh + 2*G64_BUF;

    int tid = threadIdx.x;
    int warp = tid >> 5, lane = tid & 31;
    int wm = warp & 1, wn = warp >> 1;
    int m0 = blockIdx.y * 64, n0 = blockIdx.x * 64;

    float acc[2][2][4];
#pragma unroll
    for (int i = 0; i < 2; i++)
#pragma unroll
        for (int j = 0; j < 2; j++)
#pragma unroll
            for (int k = 0; k < 4; k++) acc[i][j][k] = 0.f;

    int a_r = lane & 15, a_k = (lane >> 4) << 3;
    int b_r = ((lane >> 4) & 1)*8 + (lane & 7);
    int b_k = ((lane >> 3) & 1)*8;

    int sr = tid >> 2, sc = (tid & 3) * 8;

    int KT = K / KC;
    {
        uint32_t d = (uint32_t)((sr*SA + sc) * 2);
        cp16(aAh + d, Ah + (size_t)(m0 + sr)*K + sc);
        cp16(aAl + d, Al + (size_t)(m0 + sr)*K + sc);
        cp16(aWh + d, Wh + (size_t)(n0 + sr)*K + sc);
        cp16(aWl + d, Wl + (size_t)(n0 + sr)*K + sc);
        CP_COMMIT();
    }

    int buf = 0;
    for (int c = 0; c < KT; c++) {
        CP_WAIT0();
        __syncthreads();
        if (c + 1 < KT) {
            int k0 = (c + 1) * KC;
            uint32_t o = (uint32_t)((buf ^ 1) * G64_BUF);
            uint32_t d = o + (uint32_t)((sr*SA + sc) * 2);
            cp16(aAh + d, Ah + (size_t)(m0 + sr)*K + k0 + sc);
            cp16(aAl + d, Al + (size_t)(m0 + sr)*K + k0 + sc);
            cp16(aWh + d, Wh + (size_t)(n0 + sr)*K + k0 + sc);
            cp16(aWl + d, Wl + (size_t)(n0 + sr)*K + k0 + sc);
            CP_COMMIT();
        }

        uint32_t bAh = aAh + buf*G64_BUF, bAl = aAl + buf*G64_BUF;
        uint32_t bWh = aWh + buf*G64_BUF, bWl = aWl + buf*G64_BUF;
#pragma unroll
        for (int km = 0; km < 2; km++) {
            uint32_t ah[2][4], al[2][4];
#pragma unroll
            for (int mi = 0; mi < 2; mi++) {
                int off = ((wm*32 + mi*16 + a_r)*SA + km*16 + a_k) * 2;
                ldsm_x4(ah[mi], bAh + off);
                ldsm_x4(al[mi], bAl + off);
            }
            int boff = ((wn*16 + b_r)*SA + km*16 + b_k) * 2;
            uint32_t th[4], tl[4];
            ldsm_x4(th, bWh + boff);
            ldsm_x4(tl, bWl + boff);
            uint32_t bh[2][2] = {{th[0], th[1]}, {th[2], th[3]}};
            uint32_t bl[2][2] = {{tl[0], tl[1]}, {tl[2], tl[3]}};
#pragma unroll
            for (int mi = 0; mi < 2; mi++)
#pragma unroll
                for (int ni = 0; ni < 2; ni++) {
                    mma16816(acc[mi][ni], ah[mi], bh[ni]);
                    mma16816(acc[mi][ni], ah[mi], bl[ni]);
                    mma16816(acc[mi][ni], al[mi], bh[ni]);
                }
        }
        __syncthreads();
        buf ^= 1;
    }

#pragma unroll
    for (int mi = 0; mi < 2; mi++)
#pragma unroll
        for (int ni = 0; ni < 2; ni++)
#pragma unroll
            for (int pe = 0; pe < 2; pe++) {
                int m = m0 + wm*32 + mi*16 + (lane >> 2) + pe*8;
                int n = n0 + wn*16 + ni*8 + (lane & 3)*2;
                float v0 = acc[mi][ni][pe*2+0];
                float v1 = acc[mi][ni][pe*2+1];
                *(float2*)(C + (size_t)m*N + n) = make_float2(v0, v1);
                if (wrBf) {
                    __nv_bfloat16 h0, l0, h1, l1;
                    split2(v0, h0, l0); split2(v1, h1, l1);
                    __nv_bfloat162 hh; hh.x = h0; hh.y = h1;
                    __nv_bfloat162 ll; ll.x = l0; ll.y = l1;
                    if (wrBf == 1) {
                        *(__nv_bfloat162*)(g_bf + oChz + (size_t)m*N + n) = hh;
                        *(__nv_bfloat162*)(g_bf + oClz + (size_t)m*N + n) = ll;
                    } else {
                        // COMB: dir0 -> [m][n], dir1 -> [flip(m)][DM+n]
                        int bq = m / LSEQ, lq = m % LSEQ;
                        size_t cm; int col;
                        if (blockIdx.z == 0) { cm = (size_t)m; col = n; }
                        else { cm = (size_t)bq*LSEQ + (LSEQ-1-lq); col = DM + n; }
                        *(__nv_bfloat162*)(g_bf + B_COMBH + cm*2*DM + col) = hh;
                        *(__nv_bfloat162*)(g_bf + B_COMBL + cm*2*DM + col) = ll;
                    }
                }
            }
}

// ---------------- embedding (fp32 + bf16 hi/lo, both dirs) -------------------
__global__ void k_embed(const int* __restrict__ ids, const float* __restrict__ mask,
                        const float* __restrict__ tok, const float* __restrict__ pos) {
    int bl = blockIdx.x;
    int d  = threadIdx.x;
    int b = bl / LSEQ, l = bl % LSEQ;
    int id = ids[bl];
    float v = (tok[(size_t)id*DM + d] + pos[(size_t)l*DM + d]) * mask[bl];
    size_t i0 = (size_t)bl*DM + d;
    size_t i1 = (size_t)M2*DM + ((size_t)b*LSEQ + (LSEQ-1-l))*DM + d;
    g_scratch[OFF_H + i0] = v;
    g_scratch[OFF_H + i1] = v;
    __nv_bfloat16 hb, lb;
    split2(v, hb, lb);
    g_bf[B_ACTH + i0] = hb; g_bf[B_ACTL + i0] = lb;
    g_bf[B_ACTH + i1] = hb; g_bf[B_ACTL + i1] = lb;
}

// ---------------- conv+SiLU for B/C channels + dt softplus (shared by heads) -
__global__ __launch_bounds__(128) void k_convbc(const float* __restrict__ cw,
                                                const float* __restrict__ cbias,
                                                const float* __restrict__ dt_bias,
                                                int layer) {
    int dir = blockIdx.y;
    int bl = blockIdx.x;
    int b = bl / LSEQ, l = bl % LSEQ;
    int c = threadIdx.x;
    int li = dir*NLAYERS + layer;
    const float* zx = g_scratch + OFF_ZX + (size_t)dir*M2*DIP;
    int ch = DI + c;
    float4 w = *(const float4*)(cw + ((size_t)li*CD + ch)*4);
    float acc = cbias[(size_t)li*CD + ch];
#pragma unroll
    for (int k = 0; k < 4; k++) {
        int ls = l - 3 + k;
        if (ls >= 0)
            acc += zx[((size_t)b*LSEQ + ls)*DIP + DI + ch] * ((const float*)&w)[k];
    }
    float s = acc / (1.f + __expf(-acc));
    g_scratch[OFF_BC + ((size_t)dir*M2 + bl)*128 + c] = s;
    if (c < NH) {
        float raw = zx[(size_t)bl*DIP + DI + CD + c] + dt_bias[li*NH + c];
        float sp = (raw > 20.f) ? raw : log1pf(expf(raw));
        g_scratch[OFF_DTB + ((size_t)dir*M2 + bl)*NH + c] = sp;
    }
}

// ---------------- scan pass 1: x-conv fused + attention-form HMMA scan -------
#define SQ 72
#define SCAN_SMEM 55808

__global__ __launch_bounds__(256, 3) void k_scan1(const float* __restrict__ A_log,
                                               const float* __restrict__ Dp,
                                               const float* __restrict__ cw,
                                               const float* __restrict__ cbias,
                                               int layer) {
    extern __shared__ char sm[];
    __nv_bfloat16* sBh = (__nv_bfloat16*)(sm);
    __nv_bfloat16* sBl = (__nv_bfloat16*)(sm + 9216);
    __nv_bfloat16* sMh = (__nv_bfloat16*)(sm + 18432);
    __nv_bfloat16* sMl = (__nv_bfloat16*)(sm + 27648);
    __nv_bfloat16* sXh = (__nv_bfloat16*)(sm + 36864);
    __nv_bfloat16* sXl = (__nv_bfloat16*)(sm + 46080);
    __nv_bfloat16* sTh = sBh;
    __nv_bfloat16* sTl = sBl;
    float* sdtr = (float*)(sm + 55296);
    float* sdt  = (float*)(sm + 55552);
    float* sStage = (float*)(sm);

    int idx = blockIdx.x;
    int chunk = idx & 15; idx >>= 4;
    int hh = idx & 7; idx >>= 3;
    int b = idx & 1; int dir = idx >> 1;
    int hg = (dir*2 + b)*8 + hh;
    int tid = threadIdx.x;
    int warp = tid >> 5, lane = tid & 31;
    int li = dir*NLAYERS + layer;
    float Aa = -expf(A_log[li*NH + hh]);
    float Dv = Dp[li*NH + hh];
    const float* zx  = g_scratch + OFF_ZX  + (size_t)dir*M2*DIP + (size_t)b*LSEQ*DIP;
    const float* bc  = g_scratch + OFF_BC  + ((size_t)dir*M2 + (size_t)b*LSEQ)*128;
    const float* dtp = g_scratch + OFF_DTB + ((size_t)dir*M2 + (size_t)b*LSEQ)*NH;
    float* y         = g_scratch + OFF_Y   + (size_t)dir*M2*DI + (size_t)b*LSEQ*DI;
    float* sdt_g     = g_scratch + OFF_SDT + (size_t)hg*LSEQ;
    int s0 = chunk * QCH;

#pragma unroll
    for (int i = 0; i < 8; i++) {
        int id = tid + i*256;
        int r = id >> 5, q = id & 31;
        int c4 = q * 4;
        float4 t = *(const float4*)(bc + (size_t)(s0 + r)*128 + c4);
        float vv[4] = {t.x, t.y, t.z, t.w};
#pragma unroll
        for (int k = 0; k < 4; k++) {
            __nv_bfloat16 h, l;
            split2(vv[k], h, l);
            if (c4 < 64) { sBh[r*SQ + c4 + k] = h; sBl[r*SQ + c4 + k] = l; }
            else         { sMh[r*SQ + c4 - 64 + k] = h; sMl[r*SQ + c4 - 64 + k] = l; }
        }
    }
    {
        int cg4 = (tid & 15) * 4;
        int rb = (tid >> 4) * 4;
        int ch = hh*HD + cg4;
        float v[7][4];
#pragma unroll
        for (int k = 0; k < 7; k++) {
            int ls = s0 + rb - 3 + k;
            if (ls >= 0) {
                float4 t = *(const float4*)(zx + (size_t)ls*DIP + DI + ch);
                v[k][0]=t.x; v[k][1]=t.y; v[k][2]=t.z; v[k][3]=t.w;
            } else { v[k][0]=0.f; v[k][1]=0.f; v[k][2]=0.f; v[k][3]=0.f; }
        }
        float4 wch[4]; float bch[4];
#pragma unroll
        for (int c = 0; c < 4; c++) {
            wch[c] = *(const float4*)(cw + ((size_t)li*CD + ch + c)*4);
            bch[c] = cbias[(size_t)li*CD + ch + c];
        }
#pragma unroll
        for (int j = 0; j < 4; j++) {
            int r = rb + j;
#pragma unroll
            for (int c = 0; c < 4; c++) {
                float a = v[j][c]*wch[c].x + v[j+1][c]*wch[c].y
                        + v[j+2][c]*wch[c].z + v[j+3][c]*wch[c].w + bch[c];
                float s = a / (1.f + __expf(-a));
                __nv_bfloat16 h, l;
                split2(s, h, l);
                sXh[(cg4 + c)*SQ + r] = h; sXl[(cg4 + c)*SQ + r] = l;
            }
        }
    }
    if (tid < QCH) sdtr[tid] = dtp[(size_t)(s0 + tid)*NH + hh];
    __syncthreads();

    int wm = warp & 1, wn = warp >> 1;
    uint32_t baseBh = smem_u32(sBh), baseBl = smem_u32(sBl);
    uint32_t baseMh = smem_u32(sMh), baseMl = smem_u32(sMl);
    uint32_t baseXh = smem_u32(sXh), baseXl = smem_u32(sXl);
    uint32_t baseTh = baseBh, baseTl = baseBl;
    int a_r = lane & 15, a_k = (lane >> 4) << 3;
    int b_r = ((lane >> 4) & 1)*8 + (lane & 7);
    int b_k = ((lane >> 3) & 1)*8;

    float accG[2][2][4];
#pragma unroll
    for (int mi = 0; mi < 2; mi++)
#pragma unroll
        for (int ni = 0; ni < 2; ni++)
#pragma unroll
            for (int e = 0; e < 4; e++) accG[mi][ni][e] = 0.f;

#pragma unroll
    for (int kk = 0; kk < 4; kk++) {
        uint32_t ah[2][4], al[2][4];
#pragma unroll
        for (int mi = 0; mi < 2; mi++) {
            int off = ((wm*32 + mi*16 + a_r)*SQ + kk*16 + a_k) * 2;
            ldsm_x4(ah[mi], baseMh + off);
            ldsm_x4(al[mi], baseMl + off);
        }
        int boff = ((wn*16 + b_r)*SQ + kk*16 + b_k) * 2;
        uint32_t th[4], tl[4];
        ldsm_x4(th, baseBh + boff);
        ldsm_x4(tl, baseBl + boff);
        uint32_t bh[2][2] = {{th[0], th[1]}, {th[2], th[3]}};
        uint32_t bl[2][2] = {{tl[0], tl[1]}, {tl[2], tl[3]}};
#pragma unroll
        for (int mi = 0; mi < 2; mi++)
#pragma unroll
            for (int ni = 0; ni < 2; ni++) {
                mma16816(accG[mi][ni], ah[mi], bh[ni]);
                mma16816(accG[mi][ni], ah[mi], bl[ni]);
                mma16816(accG[mi][ni], al[mi], bh[ni]);
            }
    }
    __syncthreads();

    if (tid < QCH) {
        float s = sdtr[tid];
#pragma unroll
        for (int o = 1; o < 32; o <<= 1) {
            float t = __shfl_up_sync(0xffffffffu, s, o);
            if ((tid & 31) >= o) s += t;
        }
        sdt[tid] = s;
    }
    __syncthreads();
    if (tid >= 32 && tid < QCH) sdt[tid] += sdt[31];
    __syncthreads();
    float S = sdt[QCH-1];
    if (tid < QCH) sdt_g[s0 + tid] = sdt[tid];
    if (tid == 0) g_scratch[OFF_CSUM + hg*NCHUNK + chunk] = S;

    {
        int bi = tid >> 2, nb = (tid & 3) * 16;
        float wv = __expf(Aa * (S - sdt[bi])) * sdtr[bi];
        float fv[16];
#pragma unroll
        for (int n = 0; n < 16; n++) {
            int nn = nb + n;
            fv[n] = wv * (__bfloat162float(sBh[bi*SQ + nn]) + __bfloat162float(sBl[bi*SQ + nn]));
        }
        __syncthreads();
#pragma unroll
        for (int n = 0; n < 16; n++) {
            int nn = nb + n;
            __nv_bfloat16 h, l;
            split2(fv[n], h, l);
            sTh[nn*SQ + bi] = h; sTl[nn*SQ + bi] = l;
        }
    }

#pragma unroll
    for (int mi = 0; mi < 2; mi++)
#pragma unroll
        for (int ni = 0; ni < 2; ni++)
#pragma unroll
            for (int pe = 0; pe < 2; pe++) {
                int j  = wm*32 + mi*16 + (lane >> 2) + pe*8;
                int i0 = wn*16 + ni*8 + (lane & 3)*2;
                float m0v = 0.f, m1v = 0.f;
                if (j >= i0) {
                    m0v = accG[mi][ni][pe*2+0] * __expf(Aa*(sdt[j]-sdt[i0])) * sdtr[i0];
                    if (j == i0) m0v += Dv;
                }
                int i1 = i0 + 1;
                if (j >= i1) {
                    m1v = accG[mi][ni][pe*2+1] * __expf(Aa*(sdt[j]-sdt[i1])) * sdtr[i1];
                    if (j == i1) m1v += Dv;
                }
                __nv_bfloat16 h0, l0, h1, l1;
                split2(m0v, h0, l0); split2(m1v, h1, l1);
                __nv_bfloat162 hh2; hh2.x = h0; hh2.y = h1;
                __nv_bfloat162 ll2; ll2.x = l0; ll2.y = l1;
                *(__nv_bfloat162*)&sMh[j*SQ + i0] = hh2;
                *(__nv_bfloat162*)&sMl[j*SQ + i0] = ll2;
            }
    __syncthreads();

    float accY[2][2][4], accH[2][2][4];
#pragma unroll
    for (int mi = 0; mi < 2; mi++)
#pragma unroll
        for (int ni = 0; ni < 2; ni++)
#pragma unroll
            for (int e = 0; e < 4; e++) { accY[mi][ni][e] = 0.f; accH[mi][ni][e] = 0.f; }

#pragma unroll
    for (int kk = 0; kk < 4; kk++) {
        int boff = ((wn*16 + b_r)*SQ + kk*16 + b_k) * 2;
        uint32_t th[4], tl[4];
        ldsm_x4(th, baseXh + boff);
        ldsm_x4(tl, baseXl + boff);
        uint32_t xh[2][2] = {{th[0], th[1]}, {th[2], th[3]}};
        uint32_t xl[2][2] = {{tl[0], tl[1]}, {tl[2], tl[3]}};
        uint32_t mh[2][4], ml[2][4], hhh[2][4], hll[2][4];
#pragma unroll
        for (int mi = 0; mi < 2; mi++) {
            int off = ((wm*32 + mi*16 + a_r)*SQ + kk*16 + a_k) * 2;
            ldsm_x4(mh[mi], baseMh + off);
            ldsm_x4(ml[mi], baseMl + off);
            ldsm_x4(hhh[mi], baseTh + off);
            ldsm_x4(hll[mi], baseTl + off);
        }
#pragma unroll
        for (int mi = 0; mi < 2; mi++)
#pragma unroll
            for (int ni = 0; ni < 2; ni++) {
                mma16816(accY[mi][ni], mh[mi], xh[ni]);
                mma16816(accY[mi][ni], mh[mi], xl[ni]);
                mma16816(accY[mi][ni], ml[mi], xh[ni]);
                mma16816(accH[mi][ni], hhh[mi], xh[ni]);
                mma16816(accH[mi][ni], hhh[mi], xl[ni]);
                mma16816(accH[mi][ni], hll[mi], xh[ni]);
            }
    }

#pragma unroll
    for (int mi = 0; mi < 2; mi++)
#pragma unroll
        for (int ni = 0; ni < 2; ni++)
#pragma unroll
            for (int pe = 0; pe < 2; pe++) {
                int j = wm*32 + mi*16 + (lane >> 2) + pe*8;
                int p = wn*16 + ni*8 + (lane & 3)*2;
                *(float2*)(y + (size_t)(s0 + j)*DI + hh*HD + p) =
                    make_float2(accY[mi][ni][pe*2+0], accY[mi][ni][pe*2+1]);
            }

    __syncthreads();
#pragma unroll
    for (int mi = 0; mi < 2; mi++)
#pragma unroll
        for (int ni = 0; ni < 2; ni++)
#pragma unroll
            for (int pe = 0; pe < 2; pe++) {
                int n = wm*32 + mi*16 + (lane >> 2) + pe*8;
                int p = wn*16 + ni*8 + (lane & 3)*2;
                *(float2*)&sStage[n*66 + p] =
                    make_float2(accH[mi][ni][pe*2+0], accH[mi][ni][pe*2+1]);
            }
    __syncthreads();
    {
        float* hl = g_scratch + OFF_HLOC + ((size_t)hg*NCHUNK + chunk)*(HD*DS);
        int p = tid >> 2, nb = (tid & 3) * 16;
#pragma unroll
        for (int v2 = 0; v2 < 4; v2++) {
            int n = nb + v2*4;
            float4 o = make_float4(sStage[(n+0)*66 + p], sStage[(n+1)*66 + p],
                                   sStage[(n+2)*66 + p], sStage[(n+3)*66 + p]);
            *(float4*)(hl + (size_t)p*DS + n) = o;
        }
    }
}

// ---------------- scan pass 2: inter-chunk state carry -----------------------
__global__ __launch_bounds__(256) void k_scan2(const float* __restrict__ A_log, int layer) {
    int hg = blockIdx.x >> 4;
    int e  = (blockIdx.x & 15)*256 + threadIdx.x;
    int dir = hg >> 4, hh = hg & 7;
    int li = dir*NLAYERS + layer;
    float Aa = -expf(A_log[li*NH + hh]);
    const float* csum = g_scratch + OFF_CSUM + hg*NCHUNK;
    float* hl = g_scratch + OFF_HLOC + (size_t)hg*NCHUNK*(HD*DS) + e;
    float tmp[NCHUNK];
#pragma unroll
    for (int c = 0; c < NCHUNK; c++) tmp[c] = hl[(size_t)c*(HD*DS)];
    float carry = 0.f;
#pragma unroll
    for (int c = 0; c < NCHUNK; c++) {
        hl[(size_t)c*(HD*DS)] = carry;
        carry = carry * __expf(Aa * csum[c]) + tmp[c];
    }
}

// ---------------- scan pass 3: HMMA correction  y += cum∘(C·H_in) ------------
// grid 480: chunk = 1 + idx%15
__global__ __launch_bounds__(256) void k_scan3(const float* __restrict__ A_log, int layer) {
    __shared__ __align__(16) __nv_bfloat16 sCh[64*SQ];
    __shared__ __align__(16) __nv_bfloat16 sCl[64*SQ];
    __shared__ __align__(16) __nv_bfloat16 sHh[64*SQ];
    __shared__ __align__(16) __nv_bfloat16 sHl[64*SQ];
    __shared__ float scum[QCH];

    int idx = blockIdx.x;
    int chunk = 1 + (idx % 15); idx /= 15;
    int hh = idx & 7; idx >>= 3;
    int b = idx & 1; int dir = idx >> 1;
    int hg = (dir*2 + b)*8 + hh;
    int tid = threadIdx.x;
    int warp = tid >> 5, lane = tid & 31;
    int li = dir*NLAYERS + layer;
    float Aa = -expf(A_log[li*NH + hh]);
    const float* ccb = g_scratch + OFF_BC + ((size_t)dir*M2 + (size_t)b*LSEQ)*128 + 64;
    float* y         = g_scratch + OFF_Y  + (size_t)dir*M2*DI + (size_t)b*LSEQ*DI;
    const float* sdt_g = g_scratch + OFF_SDT + (size_t)hg*LSEQ;
    const float* hloc  = g_scratch + OFF_HLOC + ((size_t)hg*NCHUNK + chunk)*(HD*DS);
    int s0 = chunk * QCH;

#pragma unroll
    for (int i = 0; i < 4; i++) {
        int id = tid + i*256;
        int r = id >> 4, c4 = (id & 15) * 4;
        float4 cv = *(const float4*)(ccb + (size_t)(s0 + r)*128 + c4);
        float4 hv = *(const float4*)(hloc + (size_t)r*DS + c4);
        float ccv[4] = {cv.x, cv.y, cv.z, cv.w};
        float hhv[4] = {hv.x, hv.y, hv.z, hv.w};
#pragma unroll
        for (int k = 0; k < 4; k++) {
            __nv_bfloat16 h, l;
            split2(ccv[k], h, l);
            sCh[r*SQ + c4 + k] = h; sCl[r*SQ + c4 + k] = l;
            split2(hhv[k], h, l);
            sHh[r*SQ + c4 + k] = h; sHl[r*SQ + c4 + k] = l;
        }
    }
    if (tid < QCH) scum[tid] = __expf(Aa * sdt_g[s0 + tid]);
    __syncthreads();

    int wm = warp & 1, wn = warp >> 1;
    uint32_t baseCh = smem_u32(sCh), baseCl = smem_u32(sCl);
    uint32_t baseHh = smem_u32(sHh), baseHl = smem_u32(sHl);
    int a_r = lane & 15, a_k = (lane >> 4) << 3;
    int b_r = ((lane >> 4) & 1)*8 + (lane & 7);
    int b_k = ((lane >> 3) & 1)*8;

    float accY[2][2][4];
#pragma unroll
    for (int mi = 0; mi < 2; mi++)
#pragma unroll
        for (int ni = 0; ni < 2; ni++)
#pragma unroll
            for (int e = 0; e < 4; e++) accY[mi][ni][e] = 0.f;

#pragma unroll
    for (int kk = 0; kk < 4; kk++) {
        uint32_t ah[2][4], al[2][4];
#pragma unroll
        for (int mi = 0; mi < 2; mi++) {
            int off = ((wm*32 + mi*16 + a_r)*SQ + kk*16 + a_k) * 2;
            ldsm_x4(ah[mi], baseCh + off);
            ldsm_x4(al[mi], baseCl + off);
        }
        int boff = ((wn*16 + b_r)*SQ + kk*16 + b_k) * 2;
        uint32_t th[4], tl[4];
        ldsm_x4(th, baseHh + boff);
        ldsm_x4(tl, baseHl + boff);
        uint32_t bh[2][2] = {{th[0], th[1]}, {th[2], th[3]}};
        uint32_t bl[2][2] = {{tl[0], tl[1]}, {tl[2], tl[3]}};
#pragma unroll
        for (int mi = 0; mi < 2; mi++)
#pragma unroll
            for (int ni = 0; ni < 2; ni++) {
                mma16816(accY[mi][ni], ah[mi], bh[ni]);
                mma16816(accY[mi][ni], ah[mi], bl[ni]);
                mma16816(accY[mi][ni], al[mi], bh[ni]);
            }
    }

#pragma unroll
    for (int mi = 0; mi < 2; mi++)
#pragma unroll
        for (int ni = 0; ni < 2; ni++)
#pragma unroll
            for (int pe = 0; pe < 2; pe++) {
                int j = wm*32 + mi*16 + (lane >> 2) + pe*8;
                int p = wn*16 + ni*8 + (lane & 3)*2;
                float cum = scum[j];
                float* yp = y + (size_t)(s0 + j)*DI + hh*HD + p;
                float2 old = *(float2*)yp;
                old.x += cum * accY[mi][ni][pe*2+0];
                old.y += cum * accY[mi][ni][pe*2+1];
                *(float2*)yp = old;
            }
}

// ---------------- gated RMSNorm (vectorized, writes bf16 hi/lo) --------------
__global__ __launch_bounds__(128) void k_gatedrms(const float* __restrict__ nw, int layer) {
    int dir = blockIdx.y;
    int m = blockIdx.x;
    int t = threadIdx.x;
    int li = dir*NLAYERS + layer;
    int i4 = t * 4;
    float4 yv = *(const float4*)(g_scratch + OFF_Y + (size_t)dir*M2*DI + (size_t)m*DI + i4);
    float4 zv = *(const float4*)(g_scratch + OFF_ZX + (size_t)dir*M2*DIP + (size_t)m*DIP + i4);
    float g[4];
    float ss = 0.f;
#pragma unroll
    for (int k = 0; k < 4; k++) {
        float z = ((const float*)&zv)[k];
        float gv = ((const float*)&yv)[k] * (z / (1.f + __expf(-z)));
        g[k] = gv;
        ss += gv * gv;
    }
#pragma unroll
    for (int o = 16; o > 0; o >>= 1) ss += __shfl_xor_sync(0xffffffffu, ss, o);
    __shared__ float red[4];
    if ((t & 31) == 0) red[t >> 5] = ss;
    __syncthreads();
    float tot = red[0] + red[1] + red[2] + red[3];
    float inv = rsqrtf(tot * (1.f/DI) + 1e-5f);
    size_t oi = (size_t)dir*M2*DI + (size_t)m*DI + i4;
    float4 wv = *(const float4*)(nw + (size_t)li*DI + i4);
    __nv_bfloat162 hh[2], ll[2];
#pragma unroll
    for (int k = 0; k < 4; k++) {
        float o = g[k] * inv * ((const float*)&wv)[k];
        __nv_bfloat16 h, l;
        split2(o, h, l);
        ((__nv_bfloat16*)hh)[k] = h;
        ((__nv_bfloat16*)ll)[k] = l;
    }
    *(__nv_bfloat162*)(g_bf + B_NRMH + oi)     = hh[0];
    *(__nv_bfloat162*)(g_bf + B_NRMH + oi + 2) = hh[1];
    *(__nv_bfloat162*)(g_bf + B_NRML + oi)     = ll[0];
    *(__nv_bfloat162*)(g_bf + B_NRML + oi + 2) = ll[1];
}

// ---------------- gate sigmoid + fuse + LayerNorm ---------------------------
__global__ __launch_bounds__(256) void k_final(const float* __restrict__ fb,
                                               const float* __restrict__ lnw,
                                               const float* __restrict__ lnb,
                                               float* __restrict__ out) {
    int m = blockIdx.x;
    int d = threadIdx.x;
    int b = m / LSEQ, l = m % LSEQ;
    float gl0 = g_scratch[OFF_GATE + (size_t)m*2*DM + d] + fb[d];
    float gl1 = g_scratch[OFF_GATE + (size_t)m*2*DM + DM + d] + fb[DM + d];
    float gf = 1.f / (1.f + __expf(-gl0));
    float gb = 1.f / (1.f + __expf(-gl1));
    float fwd = g_scratch[OFF_H + (size_t)m*DM + d];
    float bwd = g_scratch[OFF_H + (size_t)M2*DM + ((size_t)b*LSEQ + (LSEQ-1-l))*DM + d];
    float fu = gf*fwd + gb*bwd;

    float s1 = fu, s2 = fu*fu;
#pragma unroll
    for (int o = 16; o > 0; o >>= 1) {
        s1 += __shfl_xor_sync(0xffffffffu, s1, o);
        s2 += __shfl_xor_sync(0xffffffffu, s2, o);
    }
    __shared__ float r1[8], r2[8];
    if ((d & 31) == 0) { r1[d >> 5] = s1; r2[d >> 5] = s2; }
    __syncthreads();
    if (d < 32) {
        float v1 = (d < 8) ? r1[d] : 0.f;
        float v2 = (d < 8) ? r2[d] : 0.f;
#pragma unroll
        for (int o = 4; o > 0; o >>= 1) {
            v1 += __shfl_xor_sync(0xffffffffu, v1, o);
            v2 += __shfl_xor_sync(0xffffffffu, v2, o);
        }
        if (d == 0) { r1[0] = v1; r2[0] = v2; }
    }
    __syncthreads();
    float mu = r1[0] * (1.f/DM);
    float var = r2[0] * (1.f/DM) - mu*mu;
    float inv = rsqrtf(var + 1e-5f);
    out[(size_t)m*DM + d] = (fu - mu) * inv * lnw[d] + lnb[d];
}

// ---------------------------------------------------------------------------
extern "C" void kernel_launch(void* const* d_in, const int* in_sizes, int n_in,
                              void* d_out, int out_size) {
    const int*   ids  = (const int*)d_in[0];
    const float* mask = (const float*)d_in[1];
    const float* tok  = (const float*)d_in[2];
    const float* pos  = (const float*)d_in[3];
    const float* inw  = (const float*)d_in[4];
    const float* cw   = (const float*)d_in[5];
    const float* cb   = (const float*)d_in[6];
    const float* dtb  = (const float*)d_in[7];
    const float* alog = (const float*)d_in[8];
    const float* dpar = (const float*)d_in[9];
    const float* nw   = (const float*)d_in[10];
    const float* ow   = (const float*)d_in[11];
    const float* fw   = (const float*)d_in[12];
    const float* fb   = (const float*)d_in[13];
    const float* lnw  = (const float*)d_in[14];
    const float* lnb  = (const float*)d_in[15];

    cudaFuncSetAttribute(k_scan1, cudaFuncAttributeMaxDynamicSharedMemorySize, SCAN_SMEM);
    cudaFuncSetAttribute(k_mma_gemm, cudaFuncAttributeMaxDynamicSharedMemorySize, GEMM_SMEM);
    cudaFuncSetAttribute(k_mma_gemm64, cudaFuncAttributeMaxDynamicSharedMemorySize, G64_SMEM);

    float* scr = nullptr;
    cudaGetSymbolAddress((void**)&scr, g_scratch);
    float* pH    = scr + OFF_H;
    float* pZX   = scr + OFF_ZX;
    float* pGATE = scr + OFF_GATE;

    {
        int n1 = 2*NLAYERS*DIP*DM;
        int n2 = 2*NLAYERS*DM*DI;
        int n3 = (2*DM)*(2*DM);
        int tot = n1 + n2 + n3;
        k_cvt3<<<(tot/4 + 255)/256, 256>>>(inw, n1, ow, n2, fw, n3);
    }

    k_embed<<<M2, DM>>>(ids, mask, tok, pos);

    for (int layer = 0; layer < NLAYERS; layer++) {
        k_mma_gemm<<<dim3((DIP + 63)/64, M2/128, 2), 256, GEMM_SMEM>>>(
            B_ACTH, B_ACTL,
            B_WINH + (size_t)layer*DIP*DM, B_WINL + (size_t)layer*DIP*DM,
            pZX, M2, DIP, DM,
            (long)M2*DM, (long)NLAYERS*DIP*DM, (long)M2*DIP,
            0, 0, 0);
        k_convbc<<<dim3(M2, 2), 128>>>(cw, cb, dtb, layer);
        k_scan1<<<512, 256, SCAN_SMEM>>>(alog, dpar, cw, cb, layer);
        k_scan2<<<512, 256>>>(alog, layer);
        k_scan3<<<480, 256>>>(alog, layer);
        k_gatedrms<<<dim3(M2, 2), 128>>>(nw, layer);
        int wrBf = (layer + 1 < NLAYERS) ? 1 : 2;   // 2 = write COMB directly
        k_mma_gemm64<<<dim3(DM/64, M2/64, 2), 256, G64_SMEM>>>(
            B_NRMH, B_NRML,
            B_WOUTH + (size_t)layer*DM*DI, B_WOUTL + (size_t)layer*DM*DI,
            pH, M2, DM, DI,
            (long)M2*DI, (long)NLAYERS*DM*DI, (long)M2*DM,
            B_ACTH, B_ACTL, wrBf);
    }

    k_mma_gemm64<<<dim3(2*DM/64, M2/64, 1), 256, G64_SMEM>>>(
        B_COMBH, B_COMBL, B_WFUSH, B_WFUSL,
        pGATE, M2, 2*DM, 2*DM, 0, 0, 0,
        0, 0, 0);
    k_final<<<M2, DM>>>(fb, lnw, lnb, (float*)d_out);
}